// round 12
// baseline (speedup 1.0000x reference)
#include <cuda_runtime.h>
#include <cuda_fp16.h>
#include <cstdint>

#define BB 8
#define SS 1024
#define DD 512
#define NHEADS 8
#define DHEAD 64
#define MROWS (BB*SS)   // 8192

// ---------------- scratch (no allocation allowed) ----------------
// fp16 split planes: [Qh|Ql|Kh|Kl|Vh], each [B*H][S][64]
#define PLANE ((size_t)4194304)
__device__ __half gP[5*PLANE];
__device__ __half gA[(size_t)MROWS*2048];       // [xs_h | xt_h | xs_l | xt_l]
__device__ __half gHs[(size_t)MROWS*1024];      // [H_h | H_l]
__device__ __half gBt[(size_t)3*512*1024];      // per-z W^T, k = [W1h(512)|W2h(512)]
__device__ __half gWoT[(size_t)512*512];        // Wo^T

// ---------------- warp-mma helpers ----------------
__device__ __forceinline__ void ldsm4(uint32_t* r, uint32_t addr)
{
    asm volatile("ldmatrix.sync.aligned.m8n8.x4.shared.b16 {%0,%1,%2,%3}, [%4];"
        : "=r"(r[0]), "=r"(r[1]), "=r"(r[2]), "=r"(r[3]) : "r"(addr));
}

__device__ __forceinline__ void ldsm4t(uint32_t* r, uint32_t addr)
{
    asm volatile("ldmatrix.sync.aligned.m8n8.x4.trans.shared.b16 {%0,%1,%2,%3}, [%4];"
        : "=r"(r[0]), "=r"(r[1]), "=r"(r[2]), "=r"(r[3]) : "r"(addr));
}

__device__ __forceinline__ void mma16816(float* c, const uint32_t* a, const uint32_t* b)
{
    asm volatile(
        "mma.sync.aligned.m16n8k16.row.col.f32.f16.f16.f32 "
        "{%0,%1,%2,%3}, {%4,%5,%6,%7}, {%8,%9}, {%0,%1,%2,%3};"
        : "+f"(c[0]), "+f"(c[1]), "+f"(c[2]), "+f"(c[3])
        : "r"(a[0]), "r"(a[1]), "r"(a[2]), "r"(a[3]), "r"(b[0]), "r"(b[1]));
}

__device__ __forceinline__ void split2(float2 v, uint32_t& hi, uint32_t& lo)
{
    __half hx = __float2half_rn(v.x);
    __half hy = __float2half_rn(v.y);
    float rx = v.x - __half2float(hx);
    float ry = v.y - __half2float(hy);
    hi = ((uint32_t)__half_as_ushort(hy) << 16) | (uint32_t)__half_as_ushort(hx);
    lo = ((uint32_t)__half_as_ushort(__float2half_rn(ry)) << 16)
       | (uint32_t)__half_as_ushort(__float2half_rn(rx));
}

// ---------------------------------------------------------------------------
// fused prep: [0,4096) A-split float4; [4096,4480) W transpose-pack (z 0..2);
// [4480,4544) Wo transpose-pack
// ---------------------------------------------------------------------------
__global__ void prep_all(const float* __restrict__ xs, const float* __restrict__ xt,
                         const float* __restrict__ Wqs, const float* __restrict__ Wks,
                         const float* __restrict__ Wvs, const float* __restrict__ Wqt,
                         const float* __restrict__ Wkt, const float* __restrict__ Wvt,
                         const float* __restrict__ Wo)
{
    __shared__ __half smt[64*65];
    const int bid = blockIdx.x;
    const int t = threadIdx.x;

    if (bid < 4096) {
        int idx = bid*256 + t;
        int r = idx >> 7;
        int c = (idx & 127) << 2;
        float4 a = *(const float4*)&xs[(size_t)r*DD + c];
        float4 b = *(const float4*)&xt[(size_t)r*DD + c];
        __half* row = gA + (size_t)r*2048;
        uint32_t h0, l0, h1, l1;
        split2(make_float2(a.x, a.y), h0, l0);
        split2(make_float2(a.z, a.w), h1, l1);
        *(uint2*)&row[c]        = make_uint2(h0, h1);
        *(uint2*)&row[1024 + c] = make_uint2(l0, l1);
        split2(make_float2(b.x, b.y), h0, l0);
        split2(make_float2(b.z, b.w), h1, l1);
        *(uint2*)&row[512 + c]  = make_uint2(h0, h1);
        *(uint2*)&row[1536 + c] = make_uint2(l0, l1);
        return;
    }

    int wb = bid - 4096;
    const float* src;
    __half* dst;
    int stride, n0, kbase, ks0;
    if (wb < 384) {
        int z = wb >> 7, rem = wb & 127;
        int ntile = rem >> 4, ktile = rem & 15;
        const float* W1 = (z==0) ? Wqs : ((z==1) ? Wks : Wvs);
        const float* W2 = (z==0) ? Wqt : ((z==1) ? Wkt : Wvt);
        src = (ktile < 8) ? W1 : W2;
        ks0 = (ktile & 7) * 64;
        dst = gBt + (size_t)z * 512 * 1024;
        stride = 1024;
        n0 = ntile * 64;
        kbase = ktile * 64;
    } else {
        int rem = wb - 384;
        int ntile = rem >> 3, ktile = rem & 7;
        src = Wo;
        ks0 = ktile * 64;
        dst = gWoT;
        stride = 512;
        n0 = ntile * 64;
        kbase = ktile * 64;
    }

    {
        int cc = t & 63, rr = t >> 6;
#pragma unroll
        for (int i = 0; i < 16; i++) {
            int row = rr*16 + i;
            smt[row*65 + cc] = __float2half_rn(src[(size_t)(ks0 + row)*DD + n0 + cc]);
        }
    }
    __syncthreads();
    {
        int kc = (t & 31) * 2, rn = t >> 5;
#pragma unroll
        for (int i = 0; i < 8; i++) {
            int nl = rn + i*8;
            uint32_t v = ((uint32_t)__half_as_ushort(smt[(kc+1)*65 + nl]) << 16)
                       |  (uint32_t)__half_as_ushort(smt[kc*65 + nl]);
            *(uint32_t*)&dst[(size_t)(n0 + nl)*stride + kbase + kc] = v;
        }
    }
}

// ---------------------------------------------------------------------------
// fp16 mma.sync GEMM (round-11 winner, unchanged except Q scale constant):
// 256 threads, 8 warps (2x4), warp tile 64x32, block 128x128, BK=64,
// 2-stage 48KB/stage. mode 0: QKV -> gP ; mode 1: OUT -> fp32
// ---------------------------------------------------------------------------
__global__ __launch_bounds__(256)
void mma_gemm(int mode, float* __restrict__ outp, const float* __restrict__ WKb)
{
    extern __shared__ __half smg[];

    const __half* A;
    const __half* Bt;
    int aW, bStride, nChunks, aLoOff, nAt;
    const int z = blockIdx.z;
    if (mode == 0) {
        A = gA; aW = 2048; bStride = 1024; nChunks = 16; aLoOff = 1024;
        nAt = (z == 2) ? 1 : 2;
        Bt = gBt + (size_t)z * 512 * 1024;
    } else {
        A = gHs; aW = 1024; bStride = 512; nChunks = 8; aLoOff = 512;
        nAt = 2;
        Bt = gWoT;
    }

    const int mBase = blockIdx.y * 128;
    const int nBase = blockIdx.x * 128;
    const int t    = threadIdx.x;
    const int warp = t >> 5;
    const int lane = t & 31;
    const int wm   = warp >> 2;
    const int wn   = warp & 3;

    const uint32_t sBase = (uint32_t)__cvta_generic_to_shared(smg);

    const int ldRow = t >> 3;
    const int ldSeg = t & 7;
    const uint32_t ldSw = ((uint32_t)ldRow << 7)
                        + (((uint32_t)ldSeg << 4) ^ (((uint32_t)ldRow & 7) << 4));

    float acc[4][4][4];
#pragma unroll
    for (int i = 0; i < 4; i++)
#pragma unroll
        for (int j = 0; j < 4; j++)
#pragma unroll
            for (int q = 0; q < 4; q++) acc[i][j][q] = 0.f;

#define LOAD_CHUNK(cc, buf) do { \
    const __half* Ah_ = A + (size_t)(mBase + ldRow) * aW + ((cc) << 6) + ldSeg * 8; \
    const __half* Bg_ = Bt + (size_t)(nBase + ldRow) * bStride + ((cc) << 6) + ldSeg * 8; \
    uint32_t base_ = sBase + (buf)*49152u + ldSw; \
    _Pragma("unroll") \
    for (int rr_ = 0; rr_ < 4; rr_++) { \
        asm volatile("cp.async.cg.shared.global [%0], [%1], 16;" \
            :: "r"(base_ + rr_*4096u), \
               "l"(__cvta_generic_to_global((const void*)(Ah_ + (size_t)rr_*32*aW)))); \
        if (nAt == 2) \
            asm volatile("cp.async.cg.shared.global [%0], [%1], 16;" \
                :: "r"(base_ + 16384u + rr_*4096u), \
                   "l"(__cvta_generic_to_global((const void*)(Ah_ + aLoOff + (size_t)rr_*32*aW)))); \
        asm volatile("cp.async.cg.shared.global [%0], [%1], 16;" \
            :: "r"(base_ + 32768u + rr_*4096u), \
               "l"(__cvta_generic_to_global((const void*)(Bg_ + (size_t)rr_*32*bStride)))); \
    } \
    asm volatile("cp.async.commit_group;" ::: "memory"); \
} while (0)

    LOAD_CHUNK(0, 0);
    LOAD_CHUNK(1, 1);

    const int aRowL = wm*64 + (lane & 15);
    const int aColB = (((lane >> 4) << 3)) * 2;
    const uint32_t aSw = ((uint32_t)aRowL & 7) << 4;
    const int bRowL = wn*32 + ((lane >> 4) << 3) + (lane & 7);
    const int bColB = ((((lane >> 3) & 1) << 3)) * 2;
    const uint32_t bSw = ((uint32_t)bRowL & 7) << 4;

    for (int c = 0; c < nChunks; c++) {
        if (c + 1 < nChunks) { asm volatile("cp.async.wait_group 1;" ::: "memory"); }
        else                 { asm volatile("cp.async.wait_group 0;" ::: "memory"); }
        __syncthreads();

        const uint32_t stg = sBase + (uint32_t)((c & 1) * 49152);
        const uint32_t bB  = stg + 32768u;
#pragma unroll
        for (int ks = 0; ks < 4; ks++) {
            const uint32_t kb = (uint32_t)(ks << 5);
            uint32_t bfr[4][2];
#pragma unroll
            for (int nfp = 0; nfp < 2; nfp++) {
                uint32_t r4[4];
                ldsm4(r4, bB + (uint32_t)((bRowL + nfp*16) << 7) + ((kb + bColB) ^ bSw));
                bfr[nfp*2+0][0] = r4[0]; bfr[nfp*2+0][1] = r4[1];
                bfr[nfp*2+1][0] = r4[2]; bfr[nfp*2+1][1] = r4[3];
            }
#pragma unroll
            for (int at = 0; at < 2; at++) {
                if (at == 1 && nAt == 1) break;
                const uint32_t aB = stg + (uint32_t)(at * 16384);
                uint32_t afr[4][4];
#pragma unroll
                for (int mf = 0; mf < 4; mf++)
                    ldsm4(afr[mf], aB + (uint32_t)((aRowL + mf*16) << 7) + ((kb + aColB) ^ aSw));
#pragma unroll
                for (int mf = 0; mf < 4; mf++)
#pragma unroll
                    for (int nf = 0; nf < 4; nf++)
                        mma16816(acc[mf][nf], afr[mf], bfr[nf]);
            }
        }
        __syncthreads();
        if (c + 2 < nChunks) LOAD_CHUNK(c + 2, c & 1);
    }

    const int g   = lane >> 2;
    const int tig = lane & 3;

    if (mode == 0) {
        __half* Ph = gP + (size_t)((z==0) ? 0 : (z==1) ? 2 : 4) * PLANE;
        __half* Pl = Ph + PLANE;
        const float QSC = 0.125f * 1.4426950408889634f;   // fold log2(e) for exp2 softmax
#pragma unroll
        for (int mf = 0; mf < 4; mf++) {
            int row0 = mBase + wm*64 + mf*16 + g;
            int bb = row0 >> 10, s0 = row0 & (SS-1);
#pragma unroll
            for (int nf = 0; nf < 4; nf++) {
                int col = nBase + wn*32 + nf*8 + tig*2;
                int hh = col >> 6, d = col & 63;
                float c0 = acc[mf][nf][0], c1 = acc[mf][nf][1];
                float c2 = acc[mf][nf][2], c3 = acc[mf][nf][3];
                if (z == 0) { c0 *= QSC; c1 *= QSC; c2 *= QSC; c3 *= QSC; }
                else if (z == 1) {
                    c0 += WKb[d*SS + s0];       c1 += WKb[(d+1)*SS + s0];
                    c2 += WKb[d*SS + s0 + 8];   c3 += WKb[(d+1)*SS + s0 + 8];
                }
                size_t off0 = ((size_t)(bb*NHEADS + hh)*SS + s0)*64 + d;
                uint32_t hi, lo;
                split2(make_float2(c0, c1), hi, lo);
                *(uint32_t*)&Ph[off0] = hi;
                if (z < 2) *(uint32_t*)&Pl[off0] = lo;
                split2(make_float2(c2, c3), hi, lo);
                *(uint32_t*)&Ph[off0 + 512] = hi;
                if (z < 2) *(uint32_t*)&Pl[off0 + 512] = lo;
            }
        }
    } else {
#pragma unroll
        for (int mf = 0; mf < 4; mf++) {
            int row0 = mBase + wm*64 + mf*16 + g;
#pragma unroll
            for (int nf = 0; nf < 4; nf++) {
                int col = nBase + wn*32 + nf*8 + tig*2;
                *(float2*)&outp[(size_t)row0*DD + col]
                    = make_float2(acc[mf][nf][0], acc[mf][nf][1]);
                *(float2*)&outp[(size_t)(row0+8)*DD + col]
                    = make_float2(acc[mf][nf][2], acc[mf][nf][3]);
            }
        }
    }
#undef LOAD_CHUNK
}

// ---------------------------------------------------------------------------
// fp16 causal flash attention: q-tile 128 (8 warps x 16 rows), K-TILE 128
// processed as two 64-key halves (registers unchanged), exp2-domain softmax.
// Buffer (48KB): [Kh 16K | Kl 16K | Vh 16K], 2 buffers, 1 sync per 128 keys.
// ---------------------------------------------------------------------------
__global__ __launch_bounds__(256, 2) void attn_mma()
{
    extern __shared__ __half sma[];

    const int bx = blockIdx.x;
    const int qt = 7 - (bx >> 6);
    const int bh = bx & 63;
    const int b = bh >> 3, h = bh & 7;
    const int t = threadIdx.x, warp = t >> 5, lane = t & 31;
    const int g = lane >> 2, tig = lane & 3;

    const size_t bhOff = (size_t)(b*NHEADS + h) * SS * 64;
    const __half* pQh = gP + bhOff;
    const __half* pQl = gP + PLANE   + bhOff;
    const __half* pKh = gP + 2*PLANE + bhOff;
    const __half* pKl = gP + 3*PLANE + bhOff;
    const __half* pVh = gP + 4*PLANE + bhOff;

    const int rloc0 = qt*128 + warp*16 + g;
    const int rloc1 = rloc0 + 8;

    uint32_t qh[4][4], ql[4][4];
    {
        const size_t q0 = (size_t)rloc0 * 64 + 2*tig;
        const size_t q1 = (size_t)rloc1 * 64 + 2*tig;
#pragma unroll
        for (int s = 0; s < 4; s++) {
            qh[s][0] = *(const uint32_t*)&pQh[q0 + s*16];
            qh[s][1] = *(const uint32_t*)&pQh[q1 + s*16];
            qh[s][2] = *(const uint32_t*)&pQh[q0 + s*16 + 8];
            qh[s][3] = *(const uint32_t*)&pQh[q1 + s*16 + 8];
            ql[s][0] = *(const uint32_t*)&pQl[q0 + s*16];
            ql[s][1] = *(const uint32_t*)&pQl[q1 + s*16];
            ql[s][2] = *(const uint32_t*)&pQl[q0 + s*16 + 8];
            ql[s][3] = *(const uint32_t*)&pQl[q1 + s*16 + 8];
        }
    }

    float o[8][4];
#pragma unroll
    for (int nf = 0; nf < 8; nf++)
#pragma unroll
        for (int j = 0; j < 4; j++) o[nf][j] = 0.f;
    float m0 = -1e30f, m1 = -1e30f, l0 = 0.f, l1 = 0.f;

    const uint32_t smB = (uint32_t)__cvta_generic_to_shared(sma);
    const int lr  = t >> 1;            // 0..127 key row
    const int lsg = (t & 1) * 4;       // 4 segs each
    const uint32_t swst = ((uint32_t)lr & 7) << 4;

// buffer: Kh [0,16K) Kl [16K,32K) Vh [32K,48K); row = 128 bytes
#define LOAD_TILE(kt_, buf_) do { \
    const size_t ro_ = (size_t)((kt_)*128 + lr) * 64; \
    uint32_t db_ = smB + (uint32_t)((buf_)*49152) + (uint32_t)(lr*128); \
    _Pragma("unroll") \
    for (int sg_ = 0; sg_ < 4; sg_++) { \
        int seg_ = lsg + sg_; \
        uint32_t co_ = ((uint32_t)(seg_*16)) ^ swst; \
        asm volatile("cp.async.cg.shared.global [%0], [%1], 16;" \
            :: "r"(db_ + co_),          "l"(__cvta_generic_to_global((const void*)(pKh + ro_ + seg_*8)))); \
        asm volatile("cp.async.cg.shared.global [%0], [%1], 16;" \
            :: "r"(db_ + 16384u + co_), "l"(__cvta_generic_to_global((const void*)(pKl + ro_ + seg_*8)))); \
        asm volatile("cp.async.cg.shared.global [%0], [%1], 16;" \
            :: "r"(db_ + 32768u + co_), "l"(__cvta_generic_to_global((const void*)(pVh + ro_ + seg_*8)))); \
    } \
    asm volatile("cp.async.commit_group;" ::: "memory"); \
} while (0)

    const uint32_t swf = (uint32_t)(lane & 7) << 4;
    const uint32_t kRowB = (uint32_t)((((lane>>4)<<3) | (lane&7)) * 128);
    const uint32_t kColS = (uint32_t)(((lane>>3)&1) << 4);
    const uint32_t vRowB = (uint32_t)((lane & 15) * 128);
    const uint32_t vColS = (uint32_t)((lane>>4) << 4);

    const int nkt = qt + 1;            // 128-key tiles
    LOAD_TILE(0, 0);

    for (int kt = 0; kt < nkt; kt++) {
        asm volatile("cp.async.wait_group 0;" ::: "memory");
        __syncthreads();
        if (kt + 1 < nkt) LOAD_TILE(kt + 1, (kt + 1) & 1);

        const uint32_t tileB = smB + (uint32_t)((kt & 1) * 49152);

#pragma unroll
        for (int half = 0; half < 2; half++) {
            const int key0 = kt*128 + half*64;
            const uint32_t bufB = tileB + (uint32_t)(half * 8192);
            const bool active = (qt*128 + warp*16 + 15) >= key0;
            if (!active) continue;

            float s[8][4];
#pragma unroll
            for (int nf = 0; nf < 8; nf++)
#pragma unroll
                for (int j = 0; j < 4; j++) s[nf][j] = 0.f;

#pragma unroll
            for (int nfp = 0; nfp < 4; nfp++) {
                const uint32_t rowOff = bufB + kRowB + (uint32_t)(nfp*2048);
#pragma unroll
                for (int ks = 0; ks < 4; ks++) {
                    uint32_t kr[4];
                    ldsm4(kr, rowOff + (((uint32_t)(ks*32) + kColS) ^ swf));
                    mma16816(s[2*nfp],   qh[ks], kr);
                    mma16816(s[2*nfp+1], qh[ks], kr + 2);
                    mma16816(s[2*nfp],   ql[ks], kr);
                    mma16816(s[2*nfp+1], ql[ks], kr + 2);
                    ldsm4(kr, rowOff + 16384u + (((uint32_t)(ks*32) + kColS) ^ swf));
                    mma16816(s[2*nfp],   qh[ks], kr);
                    mma16816(s[2*nfp+1], qh[ks], kr + 2);
                }
            }

            if (key0 >= qt*128) {      // diagonal block: apply causal mask
#pragma unroll
                for (int nf = 0; nf < 8; nf++) {
                    int kc = key0 + nf*8 + 2*tig;
                    if (kc     > rloc0) s[nf][0] = -1e30f;
                    if (kc + 1 > rloc0) s[nf][1] = -1e30f;
                    if (kc     > rloc1) s[nf][2] = -1e30f;
                    if (kc + 1 > rloc1) s[nf][3] = -1e30f;
                }
            }

            float mx0 = -1e30f, mx1 = -1e30f;
#pragma unroll
            for (int nf = 0; nf < 8; nf++) {
                mx0 = fmaxf(mx0, fmaxf(s[nf][0], s[nf][1]));
                mx1 = fmaxf(mx1, fmaxf(s[nf][2], s[nf][3]));
            }
            mx0 = fmaxf(mx0, __shfl_xor_sync(0xffffffffu, mx0, 1));
            mx0 = fmaxf(mx0, __shfl_xor_sync(0xffffffffu, mx0, 2));
            mx1 = fmaxf(mx1, __shfl_xor_sync(0xffffffffu, mx1, 1));
            mx1 = fmaxf(mx1, __shfl_xor_sync(0xffffffffu, mx1, 2));
            float mn0 = fmaxf(m0, mx0), mn1 = fmaxf(m1, mx1);
            float a0 = exp2f(m0 - mn0), a1 = exp2f(m1 - mn1);
            m0 = mn0; m1 = mn1;
            float sum0 = 0.f, sum1 = 0.f;
#pragma unroll
            for (int nf = 0; nf < 8; nf++) {
                s[nf][0] = exp2f(s[nf][0] - mn0);
                s[nf][1] = exp2f(s[nf][1] - mn0);
                s[nf][2] = exp2f(s[nf][2] - mn1);
                s[nf][3] = exp2f(s[nf][3] - mn1);
                sum0 += s[nf][0] + s[nf][1];
                sum1 += s[nf][2] + s[nf][3];
            }
            sum0 += __shfl_xor_sync(0xffffffffu, sum0, 1);
            sum0 += __shfl_xor_sync(0xffffffffu, sum0, 2);
            sum1 += __shfl_xor_sync(0xffffffffu, sum1, 1);
            sum1 += __shfl_xor_sync(0xffffffffu, sum1, 2);
            l0 = l0*a0 + sum0;
            l1 = l1*a1 + sum1;
#pragma unroll
            for (int nf = 0; nf < 8; nf++) {
                o[nf][0] *= a0; o[nf][1] *= a0;
                o[nf][2] *= a1; o[nf][3] *= a1;
            }

            // O += (Ph + Pl) @ Vh
#pragma unroll
            for (int sk = 0; sk < 4; sk++) {
                uint32_t ph[4], pl[4];
                split2(make_float2(s[2*sk][0],   s[2*sk][1]),   ph[0], pl[0]);
                split2(make_float2(s[2*sk][2],   s[2*sk][3]),   ph[1], pl[1]);
                split2(make_float2(s[2*sk+1][0], s[2*sk+1][1]), ph[2], pl[2]);
                split2(make_float2(s[2*sk+1][2], s[2*sk+1][3]), ph[3], pl[3]);
                const uint32_t vOff = bufB + 32768u + vRowB + (uint32_t)(sk*2048);
#pragma unroll
                for (int nb = 0; nb < 4; nb++) {
                    uint32_t vh4[4];
                    uint32_t co = (((uint32_t)(nb*32) + vColS) ^ swf);
                    ldsm4t(vh4, vOff + co);
                    mma16816(o[2*nb],   ph, vh4);
                    mma16816(o[2*nb+1], ph, vh4 + 2);
                    mma16816(o[2*nb],   pl, vh4);
                    mma16816(o[2*nb+1], pl, vh4 + 2);
                }
            }
        }
    }

    {
        float i0 = 1.f / l0, i1 = 1.f / l1;
        __half* base0 = gHs + (size_t)(b*SS + rloc0) * 1024;
        __half* base1 = gHs + (size_t)(b*SS + rloc1) * 1024;
#pragma unroll
        for (int nf = 0; nf < 8; nf++) {
            int col = h*64 + nf*8 + 2*tig;
            uint32_t hi, lo;
            split2(make_float2(o[nf][0]*i0, o[nf][1]*i0), hi, lo);
            *(uint32_t*)&base0[col]       = hi;
            *(uint32_t*)&base0[512 + col] = lo;
            split2(make_float2(o[nf][2]*i1, o[nf][3]*i1), hi, lo);
            *(uint32_t*)&base1[col]       = hi;
            *(uint32_t*)&base1[512 + col] = lo;
        }
    }
#undef LOAD_TILE
}

// ---------------------------------------------------------------------------
extern "C" void kernel_launch(void* const* d_in, const int* in_sizes, int n_in,
                              void* d_out, int out_size)
{
    const float* xs  = (const float*)d_in[0];
    const float* xt  = (const float*)d_in[1];
    const float* Wqs = (const float*)d_in[2];
    const float* Wks = (const float*)d_in[3];
    const float* Wvs = (const float*)d_in[4];
    const float* Wqt = (const float*)d_in[5];
    const float* Wkt = (const float*)d_in[6];
    const float* Wvt = (const float*)d_in[7];
    const float* WKb = (const float*)d_in[8];
    const float* Wo  = (const float*)d_in[9];
    float* out = (float*)d_out;

    const int GEMM_SMEM = 2 * 49152;      // 98304
    const int ATTN_SMEM = 2 * 49152;      // 98304
    cudaFuncSetAttribute(mma_gemm, cudaFuncAttributeMaxDynamicSharedMemorySize, GEMM_SMEM);
    cudaFuncSetAttribute(attn_mma, cudaFuncAttributeMaxDynamicSharedMemorySize, ATTN_SMEM);

    prep_all<<<4544, 256>>>(xs, xt, Wqs, Wks, Wvs, Wqt, Wkt, Wvt, Wo);

    mma_gemm<<<dim3(4, 64, 3), 256, GEMM_SMEM>>>(0, nullptr, WKb);
    attn_mma<<<512, 256, ATTN_SMEM>>>();
    mma_gemm<<<dim3(4, 64, 1), 256, GEMM_SMEM>>>(1, out, WKb);
}

// round 13
// speedup vs baseline: 1.0209x; 1.0209x over previous
#include <cuda_runtime.h>
#include <cuda_fp16.h>
#include <cstdint>

#define BB 8
#define SS 1024
#define DD 512
#define NHEADS 8
#define DHEAD 64
#define MROWS (BB*SS)   // 8192

// ---------------- scratch (no allocation allowed) ----------------
// fp16 split planes: [Qh|Ql|Kh|Kl|Vh], each [B*H][S][64]
#define PLANE ((size_t)4194304)
__device__ __half gP[5*PLANE];
__device__ __half gA[(size_t)MROWS*2048];       // [xs_h | xt_h | xs_l | xt_l]
__device__ __half gHs[(size_t)MROWS*1024];      // [H_h | H_l]
__device__ __half gBt[(size_t)3*512*1024];      // per-z W^T, k = [W1h(512)|W2h(512)]
__device__ __half gWoT[(size_t)512*512];        // Wo^T

// ---------------- warp-mma helpers ----------------
__device__ __forceinline__ void ldsm4(uint32_t* r, uint32_t addr)
{
    asm volatile("ldmatrix.sync.aligned.m8n8.x4.shared.b16 {%0,%1,%2,%3}, [%4];"
        : "=r"(r[0]), "=r"(r[1]), "=r"(r[2]), "=r"(r[3]) : "r"(addr));
}

__device__ __forceinline__ void ldsm4t(uint32_t* r, uint32_t addr)
{
    asm volatile("ldmatrix.sync.aligned.m8n8.x4.trans.shared.b16 {%0,%1,%2,%3}, [%4];"
        : "=r"(r[0]), "=r"(r[1]), "=r"(r[2]), "=r"(r[3]) : "r"(addr));
}

__device__ __forceinline__ void mma16816(float* c, const uint32_t* a, const uint32_t* b)
{
    asm volatile(
        "mma.sync.aligned.m16n8k16.row.col.f32.f16.f16.f32 "
        "{%0,%1,%2,%3}, {%4,%5,%6,%7}, {%8,%9}, {%0,%1,%2,%3};"
        : "+f"(c[0]), "+f"(c[1]), "+f"(c[2]), "+f"(c[3])
        : "r"(a[0]), "r"(a[1]), "r"(a[2]), "r"(a[3]), "r"(b[0]), "r"(b[1]));
}

__device__ __forceinline__ void split2(float2 v, uint32_t& hi, uint32_t& lo)
{
    __half hx = __float2half_rn(v.x);
    __half hy = __float2half_rn(v.y);
    float rx = v.x - __half2float(hx);
    float ry = v.y - __half2float(hy);
    hi = ((uint32_t)__half_as_ushort(hy) << 16) | (uint32_t)__half_as_ushort(hx);
    lo = ((uint32_t)__half_as_ushort(__float2half_rn(ry)) << 16)
       | (uint32_t)__half_as_ushort(__float2half_rn(rx));
}

// ---------------------------------------------------------------------------
// fused prep: [0,4096) A-split float4; [4096,4480) W transpose-pack (z 0..2);
// [4480,4544) Wo transpose-pack
// ---------------------------------------------------------------------------
__global__ void prep_all(const float* __restrict__ xs, const float* __restrict__ xt,
                         const float* __restrict__ Wqs, const float* __restrict__ Wks,
                         const float* __restrict__ Wvs, const float* __restrict__ Wqt,
                         const float* __restrict__ Wkt, const float* __restrict__ Wvt,
                         const float* __restrict__ Wo)
{
    __shared__ __half smt[64*65];
    const int bid = blockIdx.x;
    const int t = threadIdx.x;

    if (bid < 4096) {
        int idx = bid*256 + t;
        int r = idx >> 7;
        int c = (idx & 127) << 2;
        float4 a = *(const float4*)&xs[(size_t)r*DD + c];
        float4 b = *(const float4*)&xt[(size_t)r*DD + c];
        __half* row = gA + (size_t)r*2048;
        uint32_t h0, l0, h1, l1;
        split2(make_float2(a.x, a.y), h0, l0);
        split2(make_float2(a.z, a.w), h1, l1);
        *(uint2*)&row[c]        = make_uint2(h0, h1);
        *(uint2*)&row[1024 + c] = make_uint2(l0, l1);
        split2(make_float2(b.x, b.y), h0, l0);
        split2(make_float2(b.z, b.w), h1, l1);
        *(uint2*)&row[512 + c]  = make_uint2(h0, h1);
        *(uint2*)&row[1536 + c] = make_uint2(l0, l1);
        return;
    }

    int wb = bid - 4096;
    const float* src;
    __half* dst;
    int stride, n0, kbase, ks0;
    if (wb < 384) {
        int z = wb >> 7, rem = wb & 127;
        int ntile = rem >> 4, ktile = rem & 15;
        const float* W1 = (z==0) ? Wqs : ((z==1) ? Wks : Wvs);
        const float* W2 = (z==0) ? Wqt : ((z==1) ? Wkt : Wvt);
        src = (ktile < 8) ? W1 : W2;
        ks0 = (ktile & 7) * 64;
        dst = gBt + (size_t)z * 512 * 1024;
        stride = 1024;
        n0 = ntile * 64;
        kbase = ktile * 64;
    } else {
        int rem = wb - 384;
        int ntile = rem >> 3, ktile = rem & 7;
        src = Wo;
        ks0 = ktile * 64;
        dst = gWoT;
        stride = 512;
        n0 = ntile * 64;
        kbase = ktile * 64;
    }

    {
        int cc = t & 63, rr = t >> 6;
#pragma unroll
        for (int i = 0; i < 16; i++) {
            int row = rr*16 + i;
            smt[row*65 + cc] = __float2half_rn(src[(size_t)(ks0 + row)*DD + n0 + cc]);
        }
    }
    __syncthreads();
    {
        int kc = (t & 31) * 2, rn = t >> 5;
#pragma unroll
        for (int i = 0; i < 8; i++) {
            int nl = rn + i*8;
            uint32_t v = ((uint32_t)__half_as_ushort(smt[(kc+1)*65 + nl]) << 16)
                       |  (uint32_t)__half_as_ushort(smt[kc*65 + nl]);
            *(uint32_t*)&dst[(size_t)(n0 + nl)*stride + kbase + kc] = v;
        }
    }
}

// ---------------------------------------------------------------------------
// fp16 mma.sync GEMM (round-11 winner): 256 threads, 8 warps (2x4),
// warp tile 64x32, block 128x128, BK=64, 2-stage 48KB/stage.
// mode 0: QKV -> gP (Q scaled by 0.125*log2e for exp2 softmax, K bias-folded,
// V hi-only); mode 1: OUT -> fp32
// ---------------------------------------------------------------------------
__global__ __launch_bounds__(256)
void mma_gemm(int mode, float* __restrict__ outp, const float* __restrict__ WKb)
{
    extern __shared__ __half smg[];

    const __half* A;
    const __half* Bt;
    int aW, bStride, nChunks, aLoOff, nAt;
    const int z = blockIdx.z;
    if (mode == 0) {
        A = gA; aW = 2048; bStride = 1024; nChunks = 16; aLoOff = 1024;
        nAt = (z == 2) ? 1 : 2;
        Bt = gBt + (size_t)z * 512 * 1024;
    } else {
        A = gHs; aW = 1024; bStride = 512; nChunks = 8; aLoOff = 512;
        nAt = 2;
        Bt = gWoT;
    }

    const int mBase = blockIdx.y * 128;
    const int nBase = blockIdx.x * 128;
    const int t    = threadIdx.x;
    const int warp = t >> 5;
    const int lane = t & 31;
    const int wm   = warp >> 2;
    const int wn   = warp & 3;

    const uint32_t sBase = (uint32_t)__cvta_generic_to_shared(smg);

    const int ldRow = t >> 3;
    const int ldSeg = t & 7;
    const uint32_t ldSw = ((uint32_t)ldRow << 7)
                        + (((uint32_t)ldSeg << 4) ^ (((uint32_t)ldRow & 7) << 4));

    float acc[4][4][4];
#pragma unroll
    for (int i = 0; i < 4; i++)
#pragma unroll
        for (int j = 0; j < 4; j++)
#pragma unroll
            for (int q = 0; q < 4; q++) acc[i][j][q] = 0.f;

#define LOAD_CHUNK(cc, buf) do { \
    const __half* Ah_ = A + (size_t)(mBase + ldRow) * aW + ((cc) << 6) + ldSeg * 8; \
    const __half* Bg_ = Bt + (size_t)(nBase + ldRow) * bStride + ((cc) << 6) + ldSeg * 8; \
    uint32_t base_ = sBase + (buf)*49152u + ldSw; \
    _Pragma("unroll") \
    for (int rr_ = 0; rr_ < 4; rr_++) { \
        asm volatile("cp.async.cg.shared.global [%0], [%1], 16;" \
            :: "r"(base_ + rr_*4096u), \
               "l"(__cvta_generic_to_global((const void*)(Ah_ + (size_t)rr_*32*aW)))); \
        if (nAt == 2) \
            asm volatile("cp.async.cg.shared.global [%0], [%1], 16;" \
                :: "r"(base_ + 16384u + rr_*4096u), \
                   "l"(__cvta_generic_to_global((const void*)(Ah_ + aLoOff + (size_t)rr_*32*aW)))); \
        asm volatile("cp.async.cg.shared.global [%0], [%1], 16;" \
            :: "r"(base_ + 32768u + rr_*4096u), \
               "l"(__cvta_generic_to_global((const void*)(Bg_ + (size_t)rr_*32*bStride)))); \
    } \
    asm volatile("cp.async.commit_group;" ::: "memory"); \
} while (0)

    LOAD_CHUNK(0, 0);
    LOAD_CHUNK(1, 1);

    const int aRowL = wm*64 + (lane & 15);
    const int aColB = (((lane >> 4) << 3)) * 2;
    const uint32_t aSw = ((uint32_t)aRowL & 7) << 4;
    const int bRowL = wn*32 + ((lane >> 4) << 3) + (lane & 7);
    const int bColB = ((((lane >> 3) & 1) << 3)) * 2;
    const uint32_t bSw = ((uint32_t)bRowL & 7) << 4;

    for (int c = 0; c < nChunks; c++) {
        if (c + 1 < nChunks) { asm volatile("cp.async.wait_group 1;" ::: "memory"); }
        else                 { asm volatile("cp.async.wait_group 0;" ::: "memory"); }
        __syncthreads();

        const uint32_t stg = sBase + (uint32_t)((c & 1) * 49152);
        const uint32_t bB  = stg + 32768u;
#pragma unroll
        for (int ks = 0; ks < 4; ks++) {
            const uint32_t kb = (uint32_t)(ks << 5);
            uint32_t bfr[4][2];
#pragma unroll
            for (int nfp = 0; nfp < 2; nfp++) {
                uint32_t r4[4];
                ldsm4(r4, bB + (uint32_t)((bRowL + nfp*16) << 7) + ((kb + bColB) ^ bSw));
                bfr[nfp*2+0][0] = r4[0]; bfr[nfp*2+0][1] = r4[1];
                bfr[nfp*2+1][0] = r4[2]; bfr[nfp*2+1][1] = r4[3];
            }
#pragma unroll
            for (int at = 0; at < 2; at++) {
                if (at == 1 && nAt == 1) break;
                const uint32_t aB = stg + (uint32_t)(at * 16384);
                uint32_t afr[4][4];
#pragma unroll
                for (int mf = 0; mf < 4; mf++)
                    ldsm4(afr[mf], aB + (uint32_t)((aRowL + mf*16) << 7) + ((kb + aColB) ^ aSw));
#pragma unroll
                for (int mf = 0; mf < 4; mf++)
#pragma unroll
                    for (int nf = 0; nf < 4; nf++)
                        mma16816(acc[mf][nf], afr[mf], bfr[nf]);
            }
        }
        __syncthreads();
        if (c + 2 < nChunks) LOAD_CHUNK(c + 2, c & 1);
    }

    const int g   = lane >> 2;
    const int tig = lane & 3;

    if (mode == 0) {
        __half* Ph = gP + (size_t)((z==0) ? 0 : (z==1) ? 2 : 4) * PLANE;
        __half* Pl = Ph + PLANE;
        const float QSC = 0.125f * 1.4426950408889634f;   // 1/sqrt(dh) * log2(e)
#pragma unroll
        for (int mf = 0; mf < 4; mf++) {
            int row0 = mBase + wm*64 + mf*16 + g;
            int bb = row0 >> 10, s0 = row0 & (SS-1);
#pragma unroll
            for (int nf = 0; nf < 4; nf++) {
                int col = nBase + wn*32 + nf*8 + tig*2;
                int hh = col >> 6, d = col & 63;
                float c0 = acc[mf][nf][0], c1 = acc[mf][nf][1];
                float c2 = acc[mf][nf][2], c3 = acc[mf][nf][3];
                if (z == 0) { c0 *= QSC; c1 *= QSC; c2 *= QSC; c3 *= QSC; }
                else if (z == 1) {
                    c0 += WKb[d*SS + s0];       c1 += WKb[(d+1)*SS + s0];
                    c2 += WKb[d*SS + s0 + 8];   c3 += WKb[(d+1)*SS + s0 + 8];
                }
                size_t off0 = ((size_t)(bb*NHEADS + hh)*SS + s0)*64 + d;
                uint32_t hi, lo;
                split2(make_float2(c0, c1), hi, lo);
                *(uint32_t*)&Ph[off0] = hi;
                if (z < 2) *(uint32_t*)&Pl[off0] = lo;
                split2(make_float2(c2, c3), hi, lo);
                *(uint32_t*)&Ph[off0 + 512] = hi;
                if (z < 2) *(uint32_t*)&Pl[off0 + 512] = lo;
            }
        }
    } else {
#pragma unroll
        for (int mf = 0; mf < 4; mf++) {
            int row0 = mBase + wm*64 + mf*16 + g;
#pragma unroll
            for (int nf = 0; nf < 4; nf++) {
                int col = nBase + wn*32 + nf*8 + tig*2;
                *(float2*)&outp[(size_t)row0*DD + col]
                    = make_float2(acc[mf][nf][0], acc[mf][nf][1]);
                *(float2*)&outp[(size_t)(row0+8)*DD + col]
                    = make_float2(acc[mf][nf][2], acc[mf][nf][3]);
            }
        }
    }
#undef LOAD_CHUNK
}

// ---------------------------------------------------------------------------
// fp16 causal flash attention (round-11 proven structure): q-tile 128
// (8 warps x 16 rows), k-tile 64, scores 3-term, PV 2-term (Vh only),
// double-buffered 24KB smem, 1 sync/tile, exp2-domain softmax.
// ---------------------------------------------------------------------------
__global__ __launch_bounds__(256, 2) void attn_mma()
{
    extern __shared__ __half sma[];

    const int bx = blockIdx.x;
    const int qt = 7 - (bx >> 6);
    const int bh = bx & 63;
    const int b = bh >> 3, h = bh & 7;
    const int t = threadIdx.x, warp = t >> 5, lane = t & 31;
    const int g = lane >> 2, tig = lane & 3;

    const size_t bhOff = (size_t)(b*NHEADS + h) * SS * 64;
    const __half* pQh = gP + bhOff;
    const __half* pQl = gP + PLANE   + bhOff;
    const __half* pKh = gP + 2*PLANE + bhOff;
    const __half* pKl = gP + 3*PLANE + bhOff;
    const __half* pVh = gP + 4*PLANE + bhOff;

    const int rloc0 = qt*128 + warp*16 + g;
    const int rloc1 = rloc0 + 8;

    uint32_t qh[4][4], ql[4][4];
    {
        const size_t q0 = (size_t)rloc0 * 64 + 2*tig;
        const size_t q1 = (size_t)rloc1 * 64 + 2*tig;
#pragma unroll
        for (int s = 0; s < 4; s++) {
            qh[s][0] = *(const uint32_t*)&pQh[q0 + s*16];
            qh[s][1] = *(const uint32_t*)&pQh[q1 + s*16];
            qh[s][2] = *(const uint32_t*)&pQh[q0 + s*16 + 8];
            qh[s][3] = *(const uint32_t*)&pQh[q1 + s*16 + 8];
            ql[s][0] = *(const uint32_t*)&pQl[q0 + s*16];
            ql[s][1] = *(const uint32_t*)&pQl[q1 + s*16];
            ql[s][2] = *(const uint32_t*)&pQl[q0 + s*16 + 8];
            ql[s][3] = *(const uint32_t*)&pQl[q1 + s*16 + 8];
        }
    }

    float o[8][4];
#pragma unroll
    for (int nf = 0; nf < 8; nf++)
#pragma unroll
        for (int j = 0; j < 4; j++) o[nf][j] = 0.f;
    float m0 = -1e30f, m1 = -1e30f, l0 = 0.f, l1 = 0.f;

    const uint32_t smB = (uint32_t)__cvta_generic_to_shared(sma);
    const int lr8 = t >> 2;
    const int ls  = t & 3;
    const uint32_t swst = ((uint32_t)lr8 & 7) << 4;

#define LOAD_TILE(kt_, buf_) do { \
    const size_t ro_ = (size_t)((kt_)*64 + lr8) * 64; \
    uint32_t db_ = smB + (uint32_t)((buf_)*24576) + (uint32_t)(lr8*128); \
    _Pragma("unroll") \
    for (int sg_ = 0; sg_ < 2; sg_++) { \
        int seg_ = ls*2 + sg_; \
        uint32_t co_ = ((uint32_t)(seg_*16)) ^ swst; \
        asm volatile("cp.async.cg.shared.global [%0], [%1], 16;" \
            :: "r"(db_ + co_),          "l"(__cvta_generic_to_global((const void*)(pKh + ro_ + seg_*8)))); \
        asm volatile("cp.async.cg.shared.global [%0], [%1], 16;" \
            :: "r"(db_ + 8192u + co_),  "l"(__cvta_generic_to_global((const void*)(pKl + ro_ + seg_*8)))); \
        asm volatile("cp.async.cg.shared.global [%0], [%1], 16;" \
            :: "r"(db_ + 16384u + co_), "l"(__cvta_generic_to_global((const void*)(pVh + ro_ + seg_*8)))); \
    } \
    asm volatile("cp.async.commit_group;" ::: "memory"); \
} while (0)

    const uint32_t swf = (uint32_t)(lane & 7) << 4;
    const uint32_t kRowB = (uint32_t)((((lane>>4)<<3) | (lane&7)) * 128);
    const uint32_t kColS = (uint32_t)(((lane>>3)&1) << 4);
    const uint32_t vRowB = (uint32_t)((lane & 15) * 128);
    const uint32_t vColS = (uint32_t)((lane>>4) << 4);

    const int nkt = 2*qt + 2;
    LOAD_TILE(0, 0);

    for (int kt = 0; kt < nkt; kt++) {
        asm volatile("cp.async.wait_group 0;" ::: "memory");
        __syncthreads();
        if (kt + 1 < nkt) LOAD_TILE(kt + 1, (kt + 1) & 1);

        const uint32_t bufB = smB + (uint32_t)((kt & 1) * 24576);
        const bool active = (qt*128 + warp*16 + 15) >= kt*64;
        if (active) {
            float s[8][4];
#pragma unroll
            for (int nf = 0; nf < 8; nf++)
#pragma unroll
                for (int j = 0; j < 4; j++) s[nf][j] = 0.f;

#pragma unroll
            for (int nfp = 0; nfp < 4; nfp++) {
                const uint32_t rowOff = bufB + kRowB + (uint32_t)(nfp*2048);
#pragma unroll
                for (int ks = 0; ks < 4; ks++) {
                    uint32_t kr[4];
                    ldsm4(kr, rowOff + (((uint32_t)(ks*32) + kColS) ^ swf));
                    mma16816(s[2*nfp],   qh[ks], kr);
                    mma16816(s[2*nfp+1], qh[ks], kr + 2);
                    mma16816(s[2*nfp],   ql[ks], kr);
                    mma16816(s[2*nfp+1], ql[ks], kr + 2);
                    ldsm4(kr, rowOff + 8192u + (((uint32_t)(ks*32) + kColS) ^ swf));
                    mma16816(s[2*nfp],   qh[ks], kr);
                    mma16816(s[2*nfp+1], qh[ks], kr + 2);
                }
            }

            if (kt >= 2*qt) {
                const int key0 = kt*64;
#pragma unroll
                for (int nf = 0; nf < 8; nf++) {
                    int kc = key0 + nf*8 + 2*tig;
                    if (kc     > rloc0) s[nf][0] = -1e30f;
                    if (kc + 1 > rloc0) s[nf][1] = -1e30f;
                    if (kc     > rloc1) s[nf][2] = -1e30f;
                    if (kc + 1 > rloc1) s[nf][3] = -1e30f;
                }
            }

            float mx0 = -1e30f, mx1 = -1e30f;
#pragma unroll
            for (int nf = 0; nf < 8; nf++) {
                mx0 = fmaxf(mx0, fmaxf(s[nf][0], s[nf][1]));
                mx1 = fmaxf(mx1, fmaxf(s[nf][2], s[nf][3]));
            }
            mx0 = fmaxf(mx0, __shfl_xor_sync(0xffffffffu, mx0, 1));
            mx0 = fmaxf(mx0, __shfl_xor_sync(0xffffffffu, mx0, 2));
            mx1 = fmaxf(mx1, __shfl_xor_sync(0xffffffffu, mx1, 1));
            mx1 = fmaxf(mx1, __shfl_xor_sync(0xffffffffu, mx1, 2));
            float mn0 = fmaxf(m0, mx0), mn1 = fmaxf(m1, mx1);
            float a0 = exp2f(m0 - mn0), a1 = exp2f(m1 - mn1);
            m0 = mn0; m1 = mn1;
            float sum0 = 0.f, sum1 = 0.f;
#pragma unroll
            for (int nf = 0; nf < 8; nf++) {
                s[nf][0] = exp2f(s[nf][0] - mn0);
                s[nf][1] = exp2f(s[nf][1] - mn0);
                s[nf][2] = exp2f(s[nf][2] - mn1);
                s[nf][3] = exp2f(s[nf][3] - mn1);
                sum0 += s[nf][0] + s[nf][1];
                sum1 += s[nf][2] + s[nf][3];
            }
            sum0 += __shfl_xor_sync(0xffffffffu, sum0, 1);
            sum0 += __shfl_xor_sync(0xffffffffu, sum0, 2);
            sum1 += __shfl_xor_sync(0xffffffffu, sum1, 1);
            sum1 += __shfl_xor_sync(0xffffffffu, sum1, 2);
            l0 = l0*a0 + sum0;
            l1 = l1*a1 + sum1;
#pragma unroll
            for (int nf = 0; nf < 8; nf++) {
                o[nf][0] *= a0; o[nf][1] *= a0;
                o[nf][2] *= a1; o[nf][3] *= a1;
            }

            // O += (Ph + Pl) @ Vh
#pragma unroll
            for (int sk = 0; sk < 4; sk++) {
                uint32_t ph[4], pl[4];
                split2(make_float2(s[2*sk][0],   s[2*sk][1]),   ph[0], pl[0]);
                split2(make_float2(s[2*sk][2],   s[2*sk][3]),   ph[1], pl[1]);
                split2(make_float2(s[2*sk+1][0], s[2*sk+1][1]), ph[2], pl[2]);
                split2(make_float2(s[2*sk+1][2], s[2*sk+1][3]), ph[3], pl[3]);
                const uint32_t vOff = bufB + 16384u + vRowB + (uint32_t)(sk*2048);
#pragma unroll
                for (int nb = 0; nb < 4; nb++) {
                    uint32_t vh4[4];
                    uint32_t co = (((uint32_t)(nb*32) + vColS) ^ swf);
                    ldsm4t(vh4, vOff + co);
                    mma16816(o[2*nb],   ph, vh4);
                    mma16816(o[2*nb+1], ph, vh4 + 2);
                    mma16816(o[2*nb],   pl, vh4);
                    mma16816(o[2*nb+1], pl, vh4 + 2);
                }
            }
        }
    }

    {
        float i0 = 1.f / l0, i1 = 1.f / l1;
        __half* base0 = gHs + (size_t)(b*SS + rloc0) * 1024;
        __half* base1 = gHs + (size_t)(b*SS + rloc1) * 1024;
#pragma unroll
        for (int nf = 0; nf < 8; nf++) {
            int col = h*64 + nf*8 + 2*tig;
            uint32_t hi, lo;
            split2(make_float2(o[nf][0]*i0, o[nf][1]*i0), hi, lo);
            *(uint32_t*)&base0[col]       = hi;
            *(uint32_t*)&base0[512 + col] = lo;
            split2(make_float2(o[nf][2]*i1, o[nf][3]*i1), hi, lo);
            *(uint32_t*)&base1[col]       = hi;
            *(uint32_t*)&base1[512 + col] = lo;
        }
    }
#undef LOAD_TILE
}

// ---------------------------------------------------------------------------
extern "C" void kernel_launch(void* const* d_in, const int* in_sizes, int n_in,
                              void* d_out, int out_size)
{
    const float* xs  = (const float*)d_in[0];
    const float* xt  = (const float*)d_in[1];
    const float* Wqs = (const float*)d_in[2];
    const float* Wks = (const float*)d_in[3];
    const float* Wvs = (const float*)d_in[4];
    const float* Wqt = (const float*)d_in[5];
    const float* Wkt = (const float*)d_in[6];
    const float* Wvt = (const float*)d_in[7];
    const float* WKb = (const float*)d_in[8];
    const float* Wo  = (const float*)d_in[9];
    float* out = (float*)d_out;

    const int GEMM_SMEM = 2 * 49152;      // 98304
    const int ATTN_SMEM = 2 * 24576;      // 49152
    cudaFuncSetAttribute(mma_gemm, cudaFuncAttributeMaxDynamicSharedMemorySize, GEMM_SMEM);
    cudaFuncSetAttribute(attn_mma, cudaFuncAttributeMaxDynamicSharedMemorySize, ATTN_SMEM);

    prep_all<<<4544, 256>>>(xs, xt, Wqs, Wks, Wvs, Wqt, Wkt, Wvt, Wo);

    mma_gemm<<<dim3(4, 64, 3), 256, GEMM_SMEM>>>(0, nullptr, WKb);
    attn_mma<<<512, 256, ATTN_SMEM>>>();
    mma_gemm<<<dim3(4, 64, 1), 256, GEMM_SMEM>>>(1, out, WKb);
}

// round 14
// speedup vs baseline: 1.0789x; 1.0569x over previous
#include <cuda_runtime.h>
#include <cuda_fp16.h>
#include <cstdint>

#define BB 8
#define SS 1024
#define DD 512
#define NHEADS 8
#define DHEAD 64
#define MROWS (BB*SS)   // 8192

// ---------------- scratch (no allocation allowed) ----------------
// fp16 split planes: [Qh|Ql|Kh|Kl|Vh], each [B*H][S][64]
#define PLANE ((size_t)4194304)
__device__ __half gP[5*PLANE];
__device__ __half gA[(size_t)MROWS*2048];       // [xs_h | xt_h | xs_l | xt_l]
__device__ __half gHs[(size_t)MROWS*1024];      // [H_h | H_l]
__device__ __half gBt[(size_t)3*512*1024];      // per-z W^T, k = [W1h(512)|W2h(512)]
__device__ __half gWoT[(size_t)512*512];        // Wo^T

// ---------------- warp-mma helpers ----------------
__device__ __forceinline__ void ldsm4(uint32_t* r, uint32_t addr)
{
    asm volatile("ldmatrix.sync.aligned.m8n8.x4.shared.b16 {%0,%1,%2,%3}, [%4];"
        : "=r"(r[0]), "=r"(r[1]), "=r"(r[2]), "=r"(r[3]) : "r"(addr));
}

__device__ __forceinline__ void ldsm4t(uint32_t* r, uint32_t addr)
{
    asm volatile("ldmatrix.sync.aligned.m8n8.x4.trans.shared.b16 {%0,%1,%2,%3}, [%4];"
        : "=r"(r[0]), "=r"(r[1]), "=r"(r[2]), "=r"(r[3]) : "r"(addr));
}

__device__ __forceinline__ void mma16816(float* c, const uint32_t* a, const uint32_t* b)
{
    asm volatile(
        "mma.sync.aligned.m16n8k16.row.col.f32.f16.f16.f32 "
        "{%0,%1,%2,%3}, {%4,%5,%6,%7}, {%8,%9}, {%0,%1,%2,%3};"
        : "+f"(c[0]), "+f"(c[1]), "+f"(c[2]), "+f"(c[3])
        : "r"(a[0]), "r"(a[1]), "r"(a[2]), "r"(a[3]), "r"(b[0]), "r"(b[1]));
}

__device__ __forceinline__ void split2(float2 v, uint32_t& hi, uint32_t& lo)
{
    __half hx = __float2half_rn(v.x);
    __half hy = __float2half_rn(v.y);
    float rx = v.x - __half2float(hx);
    float ry = v.y - __half2float(hy);
    hi = ((uint32_t)__half_as_ushort(hy) << 16) | (uint32_t)__half_as_ushort(hx);
    lo = ((uint32_t)__half_as_ushort(__float2half_rn(ry)) << 16)
       | (uint32_t)__half_as_ushort(__float2half_rn(rx));
}

__device__ __forceinline__ uint32_t pack_h2(float lo, float hi)
{
    uint32_t r;
    asm("cvt.rn.f16x2.f32 %0, %1, %2;" : "=r"(r) : "f"(hi), "f"(lo));
    return r;
}

// ---------------------------------------------------------------------------
// fused prep: [0,4096) A-split float4; [4096,4480) W transpose-pack (z 0..2);
// [4480,4544) Wo transpose-pack
// ---------------------------------------------------------------------------
__global__ void prep_all(const float* __restrict__ xs, const float* __restrict__ xt,
                         const float* __restrict__ Wqs, const float* __restrict__ Wks,
                         const float* __restrict__ Wvs, const float* __restrict__ Wqt,
                         const float* __restrict__ Wkt, const float* __restrict__ Wvt,
                         const float* __restrict__ Wo)
{
    __shared__ __half smt[64*65];
    const int bid = blockIdx.x;
    const int t = threadIdx.x;

    if (bid < 4096) {
        int idx = bid*256 + t;
        int r = idx >> 7;
        int c = (idx & 127) << 2;
        float4 a = *(const float4*)&xs[(size_t)r*DD + c];
        float4 b = *(const float4*)&xt[(size_t)r*DD + c];
        __half* row = gA + (size_t)r*2048;
        uint32_t h0, l0, h1, l1;
        split2(make_float2(a.x, a.y), h0, l0);
        split2(make_float2(a.z, a.w), h1, l1);
        *(uint2*)&row[c]        = make_uint2(h0, h1);
        *(uint2*)&row[1024 + c] = make_uint2(l0, l1);
        split2(make_float2(b.x, b.y), h0, l0);
        split2(make_float2(b.z, b.w), h1, l1);
        *(uint2*)&row[512 + c]  = make_uint2(h0, h1);
        *(uint2*)&row[1536 + c] = make_uint2(l0, l1);
        return;
    }

    int wb = bid - 4096;
    const float* src;
    __half* dst;
    int stride, n0, kbase, ks0;
    if (wb < 384) {
        int z = wb >> 7, rem = wb & 127;
        int ntile = rem >> 4, ktile = rem & 15;
        const float* W1 = (z==0) ? Wqs : ((z==1) ? Wks : Wvs);
        const float* W2 = (z==0) ? Wqt : ((z==1) ? Wkt : Wvt);
        src = (ktile < 8) ? W1 : W2;
        ks0 = (ktile & 7) * 64;
        dst = gBt + (size_t)z * 512 * 1024;
        stride = 1024;
        n0 = ntile * 64;
        kbase = ktile * 64;
    } else {
        int rem = wb - 384;
        int ntile = rem >> 3, ktile = rem & 7;
        src = Wo;
        ks0 = ktile * 64;
        dst = gWoT;
        stride = 512;
        n0 = ntile * 64;
        kbase = ktile * 64;
    }

    {
        int cc = t & 63, rr = t >> 6;
#pragma unroll
        for (int i = 0; i < 16; i++) {
            int row = rr*16 + i;
            smt[row*65 + cc] = __float2half_rn(src[(size_t)(ks0 + row)*DD + n0 + cc]);
        }
    }
    __syncthreads();
    {
        int kc = (t & 31) * 2, rn = t >> 5;
#pragma unroll
        for (int i = 0; i < 8; i++) {
            int nl = rn + i*8;
            uint32_t v = ((uint32_t)__half_as_ushort(smt[(kc+1)*65 + nl]) << 16)
                       |  (uint32_t)__half_as_ushort(smt[kc*65 + nl]);
            *(uint32_t*)&dst[(size_t)(n0 + nl)*stride + kbase + kc] = v;
        }
    }
}

// ---------------------------------------------------------------------------
// fp16 mma.sync GEMM (round-11 winner): 256 threads, 8 warps (2x4),
// warp tile 64x32, block 128x128, BK=64, 2-stage 48KB/stage.
// mode 0: QKV -> gP ; mode 1: OUT -> fp32
// ---------------------------------------------------------------------------
__global__ __launch_bounds__(256)
void mma_gemm(int mode, float* __restrict__ outp, const float* __restrict__ WKb)
{
    extern __shared__ __half smg[];

    const __half* A;
    const __half* Bt;
    int aW, bStride, nChunks, aLoOff, nAt;
    const int z = blockIdx.z;
    if (mode == 0) {
        A = gA; aW = 2048; bStride = 1024; nChunks = 16; aLoOff = 1024;
        nAt = (z == 2) ? 1 : 2;
        Bt = gBt + (size_t)z * 512 * 1024;
    } else {
        A = gHs; aW = 1024; bStride = 512; nChunks = 8; aLoOff = 512;
        nAt = 2;
        Bt = gWoT;
    }

    const int mBase = blockIdx.y * 128;
    const int nBase = blockIdx.x * 128;
    const int t    = threadIdx.x;
    const int warp = t >> 5;
    const int lane = t & 31;
    const int wm   = warp >> 2;
    const int wn   = warp & 3;

    const uint32_t sBase = (uint32_t)__cvta_generic_to_shared(smg);

    const int ldRow = t >> 3;
    const int ldSeg = t & 7;
    const uint32_t ldSw = ((uint32_t)ldRow << 7)
                        + (((uint32_t)ldSeg << 4) ^ (((uint32_t)ldRow & 7) << 4));

    float acc[4][4][4];
#pragma unroll
    for (int i = 0; i < 4; i++)
#pragma unroll
        for (int j = 0; j < 4; j++)
#pragma unroll
            for (int q = 0; q < 4; q++) acc[i][j][q] = 0.f;

#define LOAD_CHUNK(cc, buf) do { \
    const __half* Ah_ = A + (size_t)(mBase + ldRow) * aW + ((cc) << 6) + ldSeg * 8; \
    const __half* Bg_ = Bt + (size_t)(nBase + ldRow) * bStride + ((cc) << 6) + ldSeg * 8; \
    uint32_t base_ = sBase + (buf)*49152u + ldSw; \
    _Pragma("unroll") \
    for (int rr_ = 0; rr_ < 4; rr_++) { \
        asm volatile("cp.async.cg.shared.global [%0], [%1], 16;" \
            :: "r"(base_ + rr_*4096u), \
               "l"(__cvta_generic_to_global((const void*)(Ah_ + (size_t)rr_*32*aW)))); \
        if (nAt == 2) \
            asm volatile("cp.async.cg.shared.global [%0], [%1], 16;" \
                :: "r"(base_ + 16384u + rr_*4096u), \
                   "l"(__cvta_generic_to_global((const void*)(Ah_ + aLoOff + (size_t)rr_*32*aW)))); \
        asm volatile("cp.async.cg.shared.global [%0], [%1], 16;" \
            :: "r"(base_ + 32768u + rr_*4096u), \
               "l"(__cvta_generic_to_global((const void*)(Bg_ + (size_t)rr_*32*bStride)))); \
    } \
    asm volatile("cp.async.commit_group;" ::: "memory"); \
} while (0)

    LOAD_CHUNK(0, 0);
    LOAD_CHUNK(1, 1);

    const int aRowL = wm*64 + (lane & 15);
    const int aColB = (((lane >> 4) << 3)) * 2;
    const uint32_t aSw = ((uint32_t)aRowL & 7) << 4;
    const int bRowL = wn*32 + ((lane >> 4) << 3) + (lane & 7);
    const int bColB = ((((lane >> 3) & 1) << 3)) * 2;
    const uint32_t bSw = ((uint32_t)bRowL & 7) << 4;

    for (int c = 0; c < nChunks; c++) {
        if (c + 1 < nChunks) { asm volatile("cp.async.wait_group 1;" ::: "memory"); }
        else                 { asm volatile("cp.async.wait_group 0;" ::: "memory"); }
        __syncthreads();

        const uint32_t stg = sBase + (uint32_t)((c & 1) * 49152);
        const uint32_t bB  = stg + 32768u;
#pragma unroll
        for (int ks = 0; ks < 4; ks++) {
            const uint32_t kb = (uint32_t)(ks << 5);
            uint32_t bfr[4][2];
#pragma unroll
            for (int nfp = 0; nfp < 2; nfp++) {
                uint32_t r4[4];
                ldsm4(r4, bB + (uint32_t)((bRowL + nfp*16) << 7) + ((kb + bColB) ^ bSw));
                bfr[nfp*2+0][0] = r4[0]; bfr[nfp*2+0][1] = r4[1];
                bfr[nfp*2+1][0] = r4[2]; bfr[nfp*2+1][1] = r4[3];
            }
#pragma unroll
            for (int at = 0; at < 2; at++) {
                if (at == 1 && nAt == 1) break;
                const uint32_t aB = stg + (uint32_t)(at * 16384);
                uint32_t afr[4][4];
#pragma unroll
                for (int mf = 0; mf < 4; mf++)
                    ldsm4(afr[mf], aB + (uint32_t)((aRowL + mf*16) << 7) + ((kb + aColB) ^ aSw));
#pragma unroll
                for (int mf = 0; mf < 4; mf++)
#pragma unroll
                    for (int nf = 0; nf < 4; nf++)
                        mma16816(acc[mf][nf], afr[mf], bfr[nf]);
            }
        }
        __syncthreads();
        if (c + 2 < nChunks) LOAD_CHUNK(c + 2, c & 1);
    }

    const int g   = lane >> 2;
    const int tig = lane & 3;

    if (mode == 0) {
        __half* Ph = gP + (size_t)((z==0) ? 0 : (z==1) ? 2 : 4) * PLANE;
        __half* Pl = Ph + PLANE;
        const float QSC = 0.125f * 1.4426950408889634f;   // 1/sqrt(dh) * log2(e)
#pragma unroll
        for (int mf = 0; mf < 4; mf++) {
            int row0 = mBase + wm*64 + mf*16 + g;
            int bb = row0 >> 10, s0 = row0 & (SS-1);
#pragma unroll
            for (int nf = 0; nf < 4; nf++) {
                int col = nBase + wn*32 + nf*8 + tig*2;
                int hh = col >> 6, d = col & 63;
                float c0 = acc[mf][nf][0], c1 = acc[mf][nf][1];
                float c2 = acc[mf][nf][2], c3 = acc[mf][nf][3];
                if (z == 0) { c0 *= QSC; c1 *= QSC; c2 *= QSC; c3 *= QSC; }
                else if (z == 1) {
                    c0 += WKb[d*SS + s0];       c1 += WKb[(d+1)*SS + s0];
                    c2 += WKb[d*SS + s0 + 8];   c3 += WKb[(d+1)*SS + s0 + 8];
                }
                size_t off0 = ((size_t)(bb*NHEADS + hh)*SS + s0)*64 + d;
                uint32_t hi, lo;
                split2(make_float2(c0, c1), hi, lo);
                *(uint32_t*)&Ph[off0] = hi;
                if (z < 2) *(uint32_t*)&Pl[off0] = lo;
                split2(make_float2(c2, c3), hi, lo);
                *(uint32_t*)&Ph[off0 + 512] = hi;
                if (z < 2) *(uint32_t*)&Pl[off0 + 512] = lo;
            }
        }
    } else {
#pragma unroll
        for (int mf = 0; mf < 4; mf++) {
            int row0 = mBase + wm*64 + mf*16 + g;
#pragma unroll
            for (int nf = 0; nf < 4; nf++) {
                int col = nBase + wn*32 + nf*8 + tig*2;
                *(float2*)&outp[(size_t)row0*DD + col]
                    = make_float2(acc[mf][nf][0], acc[mf][nf][1]);
                *(float2*)&outp[(size_t)(row0+8)*DD + col]
                    = make_float2(acc[mf][nf][2], acc[mf][nf][3]);
            }
        }
    }
#undef LOAD_CHUNK
}

// ---------------------------------------------------------------------------
// fp16 causal flash attention: q-tile 128 (8 warps x 16 rows), k-tile 64,
// scores 3-term, PV SINGLE-term (P fp16-rn @ Vh — V is fp16-quantized anyway),
// double-buffered 24KB smem, 1 sync/tile, exp2-domain softmax.
// ---------------------------------------------------------------------------
__global__ __launch_bounds__(256, 2) void attn_mma()
{
    extern __shared__ __half sma[];

    const int bx = blockIdx.x;
    const int qt = 7 - (bx >> 6);
    const int bh = bx & 63;
    const int b = bh >> 3, h = bh & 7;
    const int t = threadIdx.x, warp = t >> 5, lane = t & 31;
    const int g = lane >> 2, tig = lane & 3;

    const size_t bhOff = (size_t)(b*NHEADS + h) * SS * 64;
    const __half* pQh = gP + bhOff;
    const __half* pQl = gP + PLANE   + bhOff;
    const __half* pKh = gP + 2*PLANE + bhOff;
    const __half* pKl = gP + 3*PLANE + bhOff;
    const __half* pVh = gP + 4*PLANE + bhOff;

    const int rloc0 = qt*128 + warp*16 + g;
    const int rloc1 = rloc0 + 8;

    uint32_t qh[4][4], ql[4][4];
    {
        const size_t q0 = (size_t)rloc0 * 64 + 2*tig;
        const size_t q1 = (size_t)rloc1 * 64 + 2*tig;
#pragma unroll
        for (int s = 0; s < 4; s++) {
            qh[s][0] = *(const uint32_t*)&pQh[q0 + s*16];
            qh[s][1] = *(const uint32_t*)&pQh[q1 + s*16];
            qh[s][2] = *(const uint32_t*)&pQh[q0 + s*16 + 8];
            qh[s][3] = *(const uint32_t*)&pQh[q1 + s*16 + 8];
            ql[s][0] = *(const uint32_t*)&pQl[q0 + s*16];
            ql[s][1] = *(const uint32_t*)&pQl[q1 + s*16];
            ql[s][2] = *(const uint32_t*)&pQl[q0 + s*16 + 8];
            ql[s][3] = *(const uint32_t*)&pQl[q1 + s*16 + 8];
        }
    }

    float o[8][4];
#pragma unroll
    for (int nf = 0; nf < 8; nf++)
#pragma unroll
        for (int j = 0; j < 4; j++) o[nf][j] = 0.f;
    float m0 = -1e30f, m1 = -1e30f, l0 = 0.f, l1 = 0.f;

    const uint32_t smB = (uint32_t)__cvta_generic_to_shared(sma);
    const int lr8 = t >> 2;
    const int ls  = t & 3;
    const uint32_t swst = ((uint32_t)lr8 & 7) << 4;

#define LOAD_TILE(kt_, buf_) do { \
    const size_t ro_ = (size_t)((kt_)*64 + lr8) * 64; \
    uint32_t db_ = smB + (uint32_t)((buf_)*24576) + (uint32_t)(lr8*128); \
    _Pragma("unroll") \
    for (int sg_ = 0; sg_ < 2; sg_++) { \
        int seg_ = ls*2 + sg_; \
        uint32_t co_ = ((uint32_t)(seg_*16)) ^ swst; \
        asm volatile("cp.async.cg.shared.global [%0], [%1], 16;" \
            :: "r"(db_ + co_),          "l"(__cvta_generic_to_global((const void*)(pKh + ro_ + seg_*8)))); \
        asm volatile("cp.async.cg.shared.global [%0], [%1], 16;" \
            :: "r"(db_ + 8192u + co_),  "l"(__cvta_generic_to_global((const void*)(pKl + ro_ + seg_*8)))); \
        asm volatile("cp.async.cg.shared.global [%0], [%1], 16;" \
            :: "r"(db_ + 16384u + co_), "l"(__cvta_generic_to_global((const void*)(pVh + ro_ + seg_*8)))); \
    } \
    asm volatile("cp.async.commit_group;" ::: "memory"); \
} while (0)

    const uint32_t swf = (uint32_t)(lane & 7) << 4;
    const uint32_t kRowB = (uint32_t)((((lane>>4)<<3) | (lane&7)) * 128);
    const uint32_t kColS = (uint32_t)(((lane>>3)&1) << 4);
    const uint32_t vRowB = (uint32_t)((lane & 15) * 128);
    const uint32_t vColS = (uint32_t)((lane>>4) << 4);

    const int nkt = 2*qt + 2;
    LOAD_TILE(0, 0);

    for (int kt = 0; kt < nkt; kt++) {
        asm volatile("cp.async.wait_group 0;" ::: "memory");
        __syncthreads();
        if (kt + 1 < nkt) LOAD_TILE(kt + 1, (kt + 1) & 1);

        const uint32_t bufB = smB + (uint32_t)((kt & 1) * 24576);
        const bool active = (qt*128 + warp*16 + 15) >= kt*64;
        if (active) {
            float s[8][4];
#pragma unroll
            for (int nf = 0; nf < 8; nf++)
#pragma unroll
                for (int j = 0; j < 4; j++) s[nf][j] = 0.f;

#pragma unroll
            for (int nfp = 0; nfp < 4; nfp++) {
                const uint32_t rowOff = bufB + kRowB + (uint32_t)(nfp*2048);
#pragma unroll
                for (int ks = 0; ks < 4; ks++) {
                    uint32_t kr[4];
                    ldsm4(kr, rowOff + (((uint32_t)(ks*32) + kColS) ^ swf));
                    mma16816(s[2*nfp],   qh[ks], kr);
                    mma16816(s[2*nfp+1], qh[ks], kr + 2);
                    mma16816(s[2*nfp],   ql[ks], kr);
                    mma16816(s[2*nfp+1], ql[ks], kr + 2);
                    ldsm4(kr, rowOff + 8192u + (((uint32_t)(ks*32) + kColS) ^ swf));
                    mma16816(s[2*nfp],   qh[ks], kr);
                    mma16816(s[2*nfp+1], qh[ks], kr + 2);
                }
            }

            if (kt >= 2*qt) {
                const int key0 = kt*64;
#pragma unroll
                for (int nf = 0; nf < 8; nf++) {
                    int kc = key0 + nf*8 + 2*tig;
                    if (kc     > rloc0) s[nf][0] = -1e30f;
                    if (kc + 1 > rloc0) s[nf][1] = -1e30f;
                    if (kc     > rloc1) s[nf][2] = -1e30f;
                    if (kc + 1 > rloc1) s[nf][3] = -1e30f;
                }
            }

            float mx0 = -1e30f, mx1 = -1e30f;
#pragma unroll
            for (int nf = 0; nf < 8; nf++) {
                mx0 = fmaxf(mx0, fmaxf(s[nf][0], s[nf][1]));
                mx1 = fmaxf(mx1, fmaxf(s[nf][2], s[nf][3]));
            }
            mx0 = fmaxf(mx0, __shfl_xor_sync(0xffffffffu, mx0, 1));
            mx0 = fmaxf(mx0, __shfl_xor_sync(0xffffffffu, mx0, 2));
            mx1 = fmaxf(mx1, __shfl_xor_sync(0xffffffffu, mx1, 1));
            mx1 = fmaxf(mx1, __shfl_xor_sync(0xffffffffu, mx1, 2));
            float mn0 = fmaxf(m0, mx0), mn1 = fmaxf(m1, mx1);
            float a0 = exp2f(m0 - mn0), a1 = exp2f(m1 - mn1);
            m0 = mn0; m1 = mn1;
            float sum0 = 0.f, sum1 = 0.f;
#pragma unroll
            for (int nf = 0; nf < 8; nf++) {
                s[nf][0] = exp2f(s[nf][0] - mn0);
                s[nf][1] = exp2f(s[nf][1] - mn0);
                s[nf][2] = exp2f(s[nf][2] - mn1);
                s[nf][3] = exp2f(s[nf][3] - mn1);
                sum0 += s[nf][0] + s[nf][1];
                sum1 += s[nf][2] + s[nf][3];
            }
            sum0 += __shfl_xor_sync(0xffffffffu, sum0, 1);
            sum0 += __shfl_xor_sync(0xffffffffu, sum0, 2);
            sum1 += __shfl_xor_sync(0xffffffffu, sum1, 1);
            sum1 += __shfl_xor_sync(0xffffffffu, sum1, 2);
            l0 = l0*a0 + sum0;
            l1 = l1*a1 + sum1;
#pragma unroll
            for (int nf = 0; nf < 8; nf++) {
                o[nf][0] *= a0; o[nf][1] *= a0;
                o[nf][2] *= a1; o[nf][3] *= a1;
            }

            // O += P(fp16) @ Vh — single term; V already fp16-quantized
#pragma unroll
            for (int sk = 0; sk < 4; sk++) {
                uint32_t ph[4];
                ph[0] = pack_h2(s[2*sk][0],   s[2*sk][1]);
                ph[1] = pack_h2(s[2*sk][2],   s[2*sk][3]);
                ph[2] = pack_h2(s[2*sk+1][0], s[2*sk+1][1]);
                ph[3] = pack_h2(s[2*sk+1][2], s[2*sk+1][3]);
                const uint32_t vOff = bufB + 16384u + vRowB + (uint32_t)(sk*2048);
#pragma unroll
                for (int nb = 0; nb < 4; nb++) {
                    uint32_t vh4[4];
                    uint32_t co = (((uint32_t)(nb*32) + vColS) ^ swf);
                    ldsm4t(vh4, vOff + co);
                    mma16816(o[2*nb],   ph, vh4);
                    mma16816(o[2*nb+1], ph, vh4 + 2);
                }
            }
        }
    }

    {
        float i0 = 1.f / l0, i1 = 1.f / l1;
        __half* base0 = gHs + (size_t)(b*SS + rloc0) * 1024;
        __half* base1 = gHs + (size_t)(b*SS + rloc1) * 1024;
#pragma unroll
        for (int nf = 0; nf < 8; nf++) {
            int col = h*64 + nf*8 + 2*tig;
            uint32_t hi, lo;
            split2(make_float2(o[nf][0]*i0, o[nf][1]*i0), hi, lo);
            *(uint32_t*)&base0[col]       = hi;
            *(uint32_t*)&base0[512 + col] = lo;
            split2(make_float2(o[nf][2]*i1, o[nf][3]*i1), hi, lo);
            *(uint32_t*)&base1[col]       = hi;
            *(uint32_t*)&base1[512 + col] = lo;
        }
    }
#undef LOAD_TILE
}

// ---------------------------------------------------------------------------
extern "C" void kernel_launch(void* const* d_in, const int* in_sizes, int n_in,
                              void* d_out, int out_size)
{
    const float* xs  = (const float*)d_in[0];
    const float* xt  = (const float*)d_in[1];
    const float* Wqs = (const float*)d_in[2];
    const float* Wks = (const float*)d_in[3];
    const float* Wvs = (const float*)d_in[4];
    const float* Wqt = (const float*)d_in[5];
    const float* Wkt = (const float*)d_in[6];
    const float* Wvt = (const float*)d_in[7];
    const float* WKb = (const float*)d_in[8];
    const float* Wo  = (const float*)d_in[9];
    float* out = (float*)d_out;

    const int GEMM_SMEM = 2 * 49152;      // 98304
    const int ATTN_SMEM = 2 * 24576;      // 49152
    cudaFuncSetAttribute(mma_gemm, cudaFuncAttributeMaxDynamicSharedMemorySize, GEMM_SMEM);
    cudaFuncSetAttribute(attn_mma, cudaFuncAttributeMaxDynamicSharedMemorySize, ATTN_SMEM);

    prep_all<<<4544, 256>>>(xs, xt, Wqs, Wks, Wvs, Wqt, Wkt, Wvt, Wo);

    mma_gemm<<<dim3(4, 64, 3), 256, GEMM_SMEM>>>(0, nullptr, WKb);
    attn_mma<<<512, 256, ATTN_SMEM>>>();
    mma_gemm<<<dim3(4, 64, 1), 256, GEMM_SMEM>>>(1, out, WKb);
}

// round 15
// speedup vs baseline: 1.1382x; 1.0550x over previous
#include <cuda_runtime.h>
#include <cuda_fp16.h>
#include <cstdint>

#define BB 8
#define SS 1024
#define DD 512
#define NHEADS 8
#define DHEAD 64
#define MROWS (BB*SS)   // 8192

// ---------------- scratch (no allocation allowed) ----------------
// fp16 split planes: [Qh|Ql|Kh|Kl|Vh], each [B*H][S][64]
#define PLANE ((size_t)4194304)
__device__ __half gP[5*PLANE];
__device__ __half gA[(size_t)MROWS*2048];       // [xs_h | xt_h | xs_l | xt_l]
__device__ __half gHs[(size_t)MROWS*512];       // H (single fp16 plane)
__device__ __half gBt[(size_t)3*512*1024];      // per-z W^T, k = [W1h(512)|W2h(512)]
__device__ __half gWoT[(size_t)512*512];        // Wo^T

// ---------------- warp-mma helpers ----------------
__device__ __forceinline__ void ldsm4(uint32_t* r, uint32_t addr)
{
    asm volatile("ldmatrix.sync.aligned.m8n8.x4.shared.b16 {%0,%1,%2,%3}, [%4];"
        : "=r"(r[0]), "=r"(r[1]), "=r"(r[2]), "=r"(r[3]) : "r"(addr));
}

__device__ __forceinline__ void ldsm4t(uint32_t* r, uint32_t addr)
{
    asm volatile("ldmatrix.sync.aligned.m8n8.x4.trans.shared.b16 {%0,%1,%2,%3}, [%4];"
        : "=r"(r[0]), "=r"(r[1]), "=r"(r[2]), "=r"(r[3]) : "r"(addr));
}

__device__ __forceinline__ void mma16816(float* c, const uint32_t* a, const uint32_t* b)
{
    asm volatile(
        "mma.sync.aligned.m16n8k16.row.col.f32.f16.f16.f32 "
        "{%0,%1,%2,%3}, {%4,%5,%6,%7}, {%8,%9}, {%0,%1,%2,%3};"
        : "+f"(c[0]), "+f"(c[1]), "+f"(c[2]), "+f"(c[3])
        : "r"(a[0]), "r"(a[1]), "r"(a[2]), "r"(a[3]), "r"(b[0]), "r"(b[1]));
}

__device__ __forceinline__ void split2(float2 v, uint32_t& hi, uint32_t& lo)
{
    __half hx = __float2half_rn(v.x);
    __half hy = __float2half_rn(v.y);
    float rx = v.x - __half2float(hx);
    float ry = v.y - __half2float(hy);
    hi = ((uint32_t)__half_as_ushort(hy) << 16) | (uint32_t)__half_as_ushort(hx);
    lo = ((uint32_t)__half_as_ushort(__float2half_rn(ry)) << 16)
       | (uint32_t)__half_as_ushort(__float2half_rn(rx));
}

__device__ __forceinline__ uint32_t pack_h2(float lo, float hi)
{
    uint32_t r;
    asm("cvt.rn.f16x2.f32 %0, %1, %2;" : "=r"(r) : "f"(hi), "f"(lo));
    return r;
}

// ---------------------------------------------------------------------------
// fused prep: [0,4096) A-split float4; [4096,4480) W transpose-pack (z 0..2);
// [4480,4544) Wo transpose-pack
// ---------------------------------------------------------------------------
__global__ void prep_all(const float* __restrict__ xs, const float* __restrict__ xt,
                         const float* __restrict__ Wqs, const float* __restrict__ Wks,
                         const float* __restrict__ Wvs, const float* __restrict__ Wqt,
                         const float* __restrict__ Wkt, const float* __restrict__ Wvt,
                         const float* __restrict__ Wo)
{
    __shared__ __half smt[64*65];
    const int bid = blockIdx.x;
    const int t = threadIdx.x;

    if (bid < 4096) {
        int idx = bid*256 + t;
        int r = idx >> 7;
        int c = (idx & 127) << 2;
        float4 a = *(const float4*)&xs[(size_t)r*DD + c];
        float4 b = *(const float4*)&xt[(size_t)r*DD + c];
        __half* row = gA + (size_t)r*2048;
        uint32_t h0, l0, h1, l1;
        split2(make_float2(a.x, a.y), h0, l0);
        split2(make_float2(a.z, a.w), h1, l1);
        *(uint2*)&row[c]        = make_uint2(h0, h1);
        *(uint2*)&row[1024 + c] = make_uint2(l0, l1);
        split2(make_float2(b.x, b.y), h0, l0);
        split2(make_float2(b.z, b.w), h1, l1);
        *(uint2*)&row[512 + c]  = make_uint2(h0, h1);
        *(uint2*)&row[1536 + c] = make_uint2(l0, l1);
        return;
    }

    int wb = bid - 4096;
    const float* src;
    __half* dst;
    int stride, n0, kbase, ks0;
    if (wb < 384) {
        int z = wb >> 7, rem = wb & 127;
        int ntile = rem >> 4, ktile = rem & 15;
        const float* W1 = (z==0) ? Wqs : ((z==1) ? Wks : Wvs);
        const float* W2 = (z==0) ? Wqt : ((z==1) ? Wkt : Wvt);
        src = (ktile < 8) ? W1 : W2;
        ks0 = (ktile & 7) * 64;
        dst = gBt + (size_t)z * 512 * 1024;
        stride = 1024;
        n0 = ntile * 64;
        kbase = ktile * 64;
    } else {
        int rem = wb - 384;
        int ntile = rem >> 3, ktile = rem & 7;
        src = Wo;
        ks0 = ktile * 64;
        dst = gWoT;
        stride = 512;
        n0 = ntile * 64;
        kbase = ktile * 64;
    }

    {
        int cc = t & 63, rr = t >> 6;
#pragma unroll
        for (int i = 0; i < 16; i++) {
            int row = rr*16 + i;
            smt[row*65 + cc] = __float2half_rn(src[(size_t)(ks0 + row)*DD + n0 + cc]);
        }
    }
    __syncthreads();
    {
        int kc = (t & 31) * 2, rn = t >> 5;
#pragma unroll
        for (int i = 0; i < 8; i++) {
            int nl = rn + i*8;
            uint32_t v = ((uint32_t)__half_as_ushort(smt[(kc+1)*65 + nl]) << 16)
                       |  (uint32_t)__half_as_ushort(smt[kc*65 + nl]);
            *(uint32_t*)&dst[(size_t)(n0 + nl)*stride + kbase + kc] = v;
        }
    }
}

// ---------------------------------------------------------------------------
// fp16 mma.sync GEMM: 256 threads, 8 warps (2x4), warp tile 64x32,
// block 128x128, BK=64, 2-stage 48KB/stage.
// mode 0: QKV -> gP (K_eff=1024, A hi+lo except V) ; mode 1: OUT (K=512, 1-term)
// ---------------------------------------------------------------------------
__global__ __launch_bounds__(256)
void mma_gemm(int mode, float* __restrict__ outp, const float* __restrict__ WKb)
{
    extern __shared__ __half smg[];

    const __half* A;
    const __half* Bt;
    int aW, bStride, nChunks, aLoOff, nAt;
    const int z = blockIdx.z;
    if (mode == 0) {
        A = gA; aW = 2048; bStride = 1024; nChunks = 16; aLoOff = 1024;
        nAt = (z == 2) ? 1 : 2;
        Bt = gBt + (size_t)z * 512 * 1024;
    } else {
        A = gHs; aW = 512; bStride = 512; nChunks = 8; aLoOff = 0;
        nAt = 1;
        Bt = gWoT;
    }

    const int mBase = blockIdx.y * 128;
    const int nBase = blockIdx.x * 128;
    const int t    = threadIdx.x;
    const int warp = t >> 5;
    const int lane = t & 31;
    const int wm   = warp >> 2;
    const int wn   = warp & 3;

    const uint32_t sBase = (uint32_t)__cvta_generic_to_shared(smg);

    const int ldRow = t >> 3;
    const int ldSeg = t & 7;
    const uint32_t ldSw = ((uint32_t)ldRow << 7)
                        + (((uint32_t)ldSeg << 4) ^ (((uint32_t)ldRow & 7) << 4));

    float acc[4][4][4];
#pragma unroll
    for (int i = 0; i < 4; i++)
#pragma unroll
        for (int j = 0; j < 4; j++)
#pragma unroll
            for (int q = 0; q < 4; q++) acc[i][j][q] = 0.f;

#define LOAD_CHUNK(cc, buf) do { \
    const __half* Ah_ = A + (size_t)(mBase + ldRow) * aW + ((cc) << 6) + ldSeg * 8; \
    const __half* Bg_ = Bt + (size_t)(nBase + ldRow) * bStride + ((cc) << 6) + ldSeg * 8; \
    uint32_t base_ = sBase + (buf)*49152u + ldSw; \
    _Pragma("unroll") \
    for (int rr_ = 0; rr_ < 4; rr_++) { \
        asm volatile("cp.async.cg.shared.global [%0], [%1], 16;" \
            :: "r"(base_ + rr_*4096u), \
               "l"(__cvta_generic_to_global((const void*)(Ah_ + (size_t)rr_*32*aW)))); \
        if (nAt == 2) \
            asm volatile("cp.async.cg.shared.global [%0], [%1], 16;" \
                :: "r"(base_ + 16384u + rr_*4096u), \
                   "l"(__cvta_generic_to_global((const void*)(Ah_ + aLoOff + (size_t)rr_*32*aW)))); \
        asm volatile("cp.async.cg.shared.global [%0], [%1], 16;" \
            :: "r"(base_ + 32768u + rr_*4096u), \
               "l"(__cvta_generic_to_global((const void*)(Bg_ + (size_t)rr_*32*bStride)))); \
    } \
    asm volatile("cp.async.commit_group;" ::: "memory"); \
} while (0)

    LOAD_CHUNK(0, 0);
    LOAD_CHUNK(1, 1);

    const int aRowL = wm*64 + (lane & 15);
    const int aColB = (((lane >> 4) << 3)) * 2;
    const uint32_t aSw = ((uint32_t)aRowL & 7) << 4;
    const int bRowL = wn*32 + ((lane >> 4) << 3) + (lane & 7);
    const int bColB = ((((lane >> 3) & 1) << 3)) * 2;
    const uint32_t bSw = ((uint32_t)bRowL & 7) << 4;

    for (int c = 0; c < nChunks; c++) {
        if (c + 1 < nChunks) { asm volatile("cp.async.wait_group 1;" ::: "memory"); }
        else                 { asm volatile("cp.async.wait_group 0;" ::: "memory"); }
        __syncthreads();

        const uint32_t stg = sBase + (uint32_t)((c & 1) * 49152);
        const uint32_t bB  = stg + 32768u;
#pragma unroll
        for (int ks = 0; ks < 4; ks++) {
            const uint32_t kb = (uint32_t)(ks << 5);
            uint32_t bfr[4][2];
#pragma unroll
            for (int nfp = 0; nfp < 2; nfp++) {
                uint32_t r4[4];
                ldsm4(r4, bB + (uint32_t)((bRowL + nfp*16) << 7) + ((kb + bColB) ^ bSw));
                bfr[nfp*2+0][0] = r4[0]; bfr[nfp*2+0][1] = r4[1];
                bfr[nfp*2+1][0] = r4[2]; bfr[nfp*2+1][1] = r4[3];
            }
#pragma unroll
            for (int at = 0; at < 2; at++) {
                if (at == 1 && nAt == 1) break;
                const uint32_t aB = stg + (uint32_t)(at * 16384);
                uint32_t afr[4][4];
#pragma unroll
                for (int mf = 0; mf < 4; mf++)
                    ldsm4(afr[mf], aB + (uint32_t)((aRowL + mf*16) << 7) + ((kb + aColB) ^ aSw));
#pragma unroll
                for (int mf = 0; mf < 4; mf++)
#pragma unroll
                    for (int nf = 0; nf < 4; nf++)
                        mma16816(acc[mf][nf], afr[mf], bfr[nf]);
            }
        }
        __syncthreads();
        if (c + 2 < nChunks) LOAD_CHUNK(c + 2, c & 1);
    }

    const int g   = lane >> 2;
    const int tig = lane & 3;

    if (mode == 0) {
        __half* Ph = gP + (size_t)((z==0) ? 0 : (z==1) ? 2 : 4) * PLANE;
        __half* Pl = Ph + PLANE;
        const float QSC = 0.125f * 1.4426950408889634f;   // 1/sqrt(dh) * log2(e)
#pragma unroll
        for (int mf = 0; mf < 4; mf++) {
            int row0 = mBase + wm*64 + mf*16 + g;
            int bb = row0 >> 10, s0 = row0 & (SS-1);
#pragma unroll
            for (int nf = 0; nf < 4; nf++) {
                int col = nBase + wn*32 + nf*8 + tig*2;
                int hh = col >> 6, d = col & 63;
                float c0 = acc[mf][nf][0], c1 = acc[mf][nf][1];
                float c2 = acc[mf][nf][2], c3 = acc[mf][nf][3];
                if (z == 0) { c0 *= QSC; c1 *= QSC; c2 *= QSC; c3 *= QSC; }
                else if (z == 1) {
                    c0 += WKb[d*SS + s0];       c1 += WKb[(d+1)*SS + s0];
                    c2 += WKb[d*SS + s0 + 8];   c3 += WKb[(d+1)*SS + s0 + 8];
                }
                size_t off0 = ((size_t)(bb*NHEADS + hh)*SS + s0)*64 + d;
                uint32_t hi, lo;
                split2(make_float2(c0, c1), hi, lo);
                *(uint32_t*)&Ph[off0] = hi;
                if (z < 2) *(uint32_t*)&Pl[off0] = lo;
                split2(make_float2(c2, c3), hi, lo);
                *(uint32_t*)&Ph[off0 + 512] = hi;
                if (z < 2) *(uint32_t*)&Pl[off0 + 512] = lo;
            }
        }
    } else {
#pragma unroll
        for (int mf = 0; mf < 4; mf++) {
            int row0 = mBase + wm*64 + mf*16 + g;
#pragma unroll
            for (int nf = 0; nf < 4; nf++) {
                int col = nBase + wn*32 + nf*8 + tig*2;
                *(float2*)&outp[(size_t)row0*DD + col]
                    = make_float2(acc[mf][nf][0], acc[mf][nf][1]);
                *(float2*)&outp[(size_t)(row0+8)*DD + col]
                    = make_float2(acc[mf][nf][2], acc[mf][nf][3]);
            }
        }
    }
#undef LOAD_CHUNK
}

// ---------------------------------------------------------------------------
// fp16 causal flash attention: q-tile 128 (8 warps x 16 rows), k-tile 64,
// scores 3-term, PV single-term, exp2 softmax, H written as single fp16 plane.
// ---------------------------------------------------------------------------
__global__ __launch_bounds__(256, 2) void attn_mma()
{
    extern __shared__ __half sma[];

    const int bx = blockIdx.x;
    const int qt = 7 - (bx >> 6);
    const int bh = bx & 63;
    const int b = bh >> 3, h = bh & 7;
    const int t = threadIdx.x, warp = t >> 5, lane = t & 31;
    const int g = lane >> 2, tig = lane & 3;

    const size_t bhOff = (size_t)(b*NHEADS + h) * SS * 64;
    const __half* pQh = gP + bhOff;
    const __half* pQl = gP + PLANE   + bhOff;
    const __half* pKh = gP + 2*PLANE + bhOff;
    const __half* pKl = gP + 3*PLANE + bhOff;
    const __half* pVh = gP + 4*PLANE + bhOff;

    const int rloc0 = qt*128 + warp*16 + g;
    const int rloc1 = rloc0 + 8;

    uint32_t qh[4][4], ql[4][4];
    {
        const size_t q0 = (size_t)rloc0 * 64 + 2*tig;
        const size_t q1 = (size_t)rloc1 * 64 + 2*tig;
#pragma unroll
        for (int s = 0; s < 4; s++) {
            qh[s][0] = *(const uint32_t*)&pQh[q0 + s*16];
            qh[s][1] = *(const uint32_t*)&pQh[q1 + s*16];
            qh[s][2] = *(const uint32_t*)&pQh[q0 + s*16 + 8];
            qh[s][3] = *(const uint32_t*)&pQh[q1 + s*16 + 8];
            ql[s][0] = *(const uint32_t*)&pQl[q0 + s*16];
            ql[s][1] = *(const uint32_t*)&pQl[q1 + s*16];
            ql[s][2] = *(const uint32_t*)&pQl[q0 + s*16 + 8];
            ql[s][3] = *(const uint32_t*)&pQl[q1 + s*16 + 8];
        }
    }

    float o[8][4];
#pragma unroll
    for (int nf = 0; nf < 8; nf++)
#pragma unroll
        for (int j = 0; j < 4; j++) o[nf][j] = 0.f;
    float m0 = -1e30f, m1 = -1e30f, l0 = 0.f, l1 = 0.f;

    const uint32_t smB = (uint32_t)__cvta_generic_to_shared(sma);
    const int lr8 = t >> 2;
    const int ls  = t & 3;
    const uint32_t swst = ((uint32_t)lr8 & 7) << 4;

#define LOAD_TILE(kt_, buf_) do { \
    const size_t ro_ = (size_t)((kt_)*64 + lr8) * 64; \
    uint32_t db_ = smB + (uint32_t)((buf_)*24576) + (uint32_t)(lr8*128); \
    _Pragma("unroll") \
    for (int sg_ = 0; sg_ < 2; sg_++) { \
        int seg_ = ls*2 + sg_; \
        uint32_t co_ = ((uint32_t)(seg_*16)) ^ swst; \
        asm volatile("cp.async.cg.shared.global [%0], [%1], 16;" \
            :: "r"(db_ + co_),          "l"(__cvta_generic_to_global((const void*)(pKh + ro_ + seg_*8)))); \
        asm volatile("cp.async.cg.shared.global [%0], [%1], 16;" \
            :: "r"(db_ + 8192u + co_),  "l"(__cvta_generic_to_global((const void*)(pKl + ro_ + seg_*8)))); \
        asm volatile("cp.async.cg.shared.global [%0], [%1], 16;" \
            :: "r"(db_ + 16384u + co_), "l"(__cvta_generic_to_global((const void*)(pVh + ro_ + seg_*8)))); \
    } \
    asm volatile("cp.async.commit_group;" ::: "memory"); \
} while (0)

    const uint32_t swf = (uint32_t)(lane & 7) << 4;
    const uint32_t kRowB = (uint32_t)((((lane>>4)<<3) | (lane&7)) * 128);
    const uint32_t kColS = (uint32_t)(((lane>>3)&1) << 4);
    const uint32_t vRowB = (uint32_t)((lane & 15) * 128);
    const uint32_t vColS = (uint32_t)((lane>>4) << 4);

    const int nkt = 2*qt + 2;
    LOAD_TILE(0, 0);

    for (int kt = 0; kt < nkt; kt++) {
        asm volatile("cp.async.wait_group 0;" ::: "memory");
        __syncthreads();
        if (kt + 1 < nkt) LOAD_TILE(kt + 1, (kt + 1) & 1);

        const uint32_t bufB = smB + (uint32_t)((kt & 1) * 24576);
        const bool active = (qt*128 + warp*16 + 15) >= kt*64;
        if (active) {
            float s[8][4];
#pragma unroll
            for (int nf = 0; nf < 8; nf++)
#pragma unroll
                for (int j = 0; j < 4; j++) s[nf][j] = 0.f;

#pragma unroll
            for (int nfp = 0; nfp < 4; nfp++) {
                const uint32_t rowOff = bufB + kRowB + (uint32_t)(nfp*2048);
#pragma unroll
                for (int ks = 0; ks < 4; ks++) {
                    uint32_t kr[4];
                    ldsm4(kr, rowOff + (((uint32_t)(ks*32) + kColS) ^ swf));
                    mma16816(s[2*nfp],   qh[ks], kr);
                    mma16816(s[2*nfp+1], qh[ks], kr + 2);
                    mma16816(s[2*nfp],   ql[ks], kr);
                    mma16816(s[2*nfp+1], ql[ks], kr + 2);
                    ldsm4(kr, rowOff + 8192u + (((uint32_t)(ks*32) + kColS) ^ swf));
                    mma16816(s[2*nfp],   qh[ks], kr);
                    mma16816(s[2*nfp+1], qh[ks], kr + 2);
                }
            }

            if (kt >= 2*qt) {
                const int key0 = kt*64;
#pragma unroll
                for (int nf = 0; nf < 8; nf++) {
                    int kc = key0 + nf*8 + 2*tig;
                    if (kc     > rloc0) s[nf][0] = -1e30f;
                    if (kc + 1 > rloc0) s[nf][1] = -1e30f;
                    if (kc     > rloc1) s[nf][2] = -1e30f;
                    if (kc + 1 > rloc1) s[nf][3] = -1e30f;
                }
            }

            float mx0 = -1e30f, mx1 = -1e30f;
#pragma unroll
            for (int nf = 0; nf < 8; nf++) {
                mx0 = fmaxf(mx0, fmaxf(s[nf][0], s[nf][1]));
                mx1 = fmaxf(mx1, fmaxf(s[nf][2], s[nf][3]));
            }
            mx0 = fmaxf(mx0, __shfl_xor_sync(0xffffffffu, mx0, 1));
            mx0 = fmaxf(mx0, __shfl_xor_sync(0xffffffffu, mx0, 2));
            mx1 = fmaxf(mx1, __shfl_xor_sync(0xffffffffu, mx1, 1));
            mx1 = fmaxf(mx1, __shfl_xor_sync(0xffffffffu, mx1, 2));
            float mn0 = fmaxf(m0, mx0), mn1 = fmaxf(m1, mx1);
            float a0 = exp2f(m0 - mn0), a1 = exp2f(m1 - mn1);
            m0 = mn0; m1 = mn1;
            float sum0 = 0.f, sum1 = 0.f;
#pragma unroll
            for (int nf = 0; nf < 8; nf++) {
                s[nf][0] = exp2f(s[nf][0] - mn0);
                s[nf][1] = exp2f(s[nf][1] - mn0);
                s[nf][2] = exp2f(s[nf][2] - mn1);
                s[nf][3] = exp2f(s[nf][3] - mn1);
                sum0 += s[nf][0] + s[nf][1];
                sum1 += s[nf][2] + s[nf][3];
            }
            sum0 += __shfl_xor_sync(0xffffffffu, sum0, 1);
            sum0 += __shfl_xor_sync(0xffffffffu, sum0, 2);
            sum1 += __shfl_xor_sync(0xffffffffu, sum1, 1);
            sum1 += __shfl_xor_sync(0xffffffffu, sum1, 2);
            l0 = l0*a0 + sum0;
            l1 = l1*a1 + sum1;
#pragma unroll
            for (int nf = 0; nf < 8; nf++) {
                o[nf][0] *= a0; o[nf][1] *= a0;
                o[nf][2] *= a1; o[nf][3] *= a1;
            }

            // O += P(fp16) @ Vh
#pragma unroll
            for (int sk = 0; sk < 4; sk++) {
                uint32_t ph[4];
                ph[0] = pack_h2(s[2*sk][0],   s[2*sk][1]);
                ph[1] = pack_h2(s[2*sk][2],   s[2*sk][3]);
                ph[2] = pack_h2(s[2*sk+1][0], s[2*sk+1][1]);
                ph[3] = pack_h2(s[2*sk+1][2], s[2*sk+1][3]);
                const uint32_t vOff = bufB + 16384u + vRowB + (uint32_t)(sk*2048);
#pragma unroll
                for (int nb = 0; nb < 4; nb++) {
                    uint32_t vh4[4];
                    uint32_t co = (((uint32_t)(nb*32) + vColS) ^ swf);
                    ldsm4t(vh4, vOff + co);
                    mma16816(o[2*nb],   ph, vh4);
                    mma16816(o[2*nb+1], ph, vh4 + 2);
                }
            }
        }
    }

    {
        float i0 = 1.f / l0, i1 = 1.f / l1;
        __half* base0 = gHs + (size_t)(b*SS + rloc0) * 512;
        __half* base1 = gHs + (size_t)(b*SS + rloc1) * 512;
#pragma unroll
        for (int nf = 0; nf < 8; nf++) {
            int col = h*64 + nf*8 + 2*tig;
            *(uint32_t*)&base0[col] = pack_h2(o[nf][0]*i0, o[nf][1]*i0);
            *(uint32_t*)&base1[col] = pack_h2(o[nf][2]*i1, o[nf][3]*i1);
        }
    }
#undef LOAD_TILE
}

// ---------------------------------------------------------------------------
extern "C" void kernel_launch(void* const* d_in, const int* in_sizes, int n_in,
                              void* d_out, int out_size)
{
    const float* xs  = (const float*)d_in[0];
    const float* xt  = (const float*)d_in[1];
    const float* Wqs = (const float*)d_in[2];
    const float* Wks = (const float*)d_in[3];
    const float* Wvs = (const float*)d_in[4];
    const float* Wqt = (const float*)d_in[5];
    const float* Wkt = (const float*)d_in[6];
    const float* Wvt = (const float*)d_in[7];
    const float* WKb = (const float*)d_in[8];
    const float* Wo  = (const float*)d_in[9];
    float* out = (float*)d_out;

    const int GEMM_SMEM = 2 * 49152;      // 98304
    const int ATTN_SMEM = 2 * 24576;      // 49152
    cudaFuncSetAttribute(mma_gemm, cudaFuncAttributeMaxDynamicSharedMemorySize, GEMM_SMEM);
    cudaFuncSetAttribute(attn_mma, cudaFuncAttributeMaxDynamicSharedMemorySize, ATTN_SMEM);

    prep_all<<<4544, 256>>>(xs, xt, Wqs, Wks, Wvs, Wqt, Wkt, Wvt, Wo);

    mma_gemm<<<dim3(4, 64, 3), 256, GEMM_SMEM>>>(0, nullptr, WKb);
    attn_mma<<<512, 256, ATTN_SMEM>>>();
    mma_gemm<<<dim3(4, 64, 1), 256, GEMM_SMEM>>>(1, out, WKb);
}